// round 8
// baseline (speedup 1.0000x reference)
#include <cuda_runtime.h>
#include <math.h>

#define NN 10000
#define NE 160000

// ---------------- device scratch (no runtime allocation allowed) ----------------
__device__ float g_CG[615];
__device__ float g_w[(size_t)NE * 252];
__device__ float g_t[(size_t)NN * 130];
__device__ float g_h1[(size_t)NN * 130];
__device__ float g_h2[(size_t)NN * 130];

// ---------------- compile-time path tables ----------------
struct PathC { int li, fOff, mul, cgOff, yBase, nj, wOff, ucat; };
__constant__ PathC c_P[21] = {
  // T0..T2: conv1 lo=0,1,2 (input mul=8, li=0)
  {0,0,8,0,0,1,0,0},
  {0,0,8,1,1,3,8,0},
  {0,0,8,10,4,5,16,0},
  // T3: conv2 lo=0
  {0,0,32,0,0,1,0,0},{1,32,16,44,1,3,112,32},{2,80,10,390,4,5,222,48},
  // T4: conv2 lo=1
  {0,0,32,1,1,3,32,0},{1,32,16,35,0,1,96,32},{1,32,16,53,1,3,128,48},
  {1,32,16,125,4,5,160,64},{2,80,10,270,1,3,202,80},{2,80,10,415,4,5,232,90},
  // T5: conv2 lo=2
  {0,0,32,10,4,5,64,0},{1,32,16,80,1,3,144,32},{1,32,16,170,4,5,176,48},
  {2,80,10,245,0,1,192,64},{2,80,10,315,1,3,212,74},{2,80,10,490,4,5,242,84},
  // T6: conv3 lo=0
  {0,0,32,0,0,1,0,0},{1,32,16,44,1,3,32,32},{2,80,10,390,4,5,48,48}
};
__constant__ int c_Toff[7] = {0,1,2,3,6,12,18};
__constant__ int c_Tnum[7] = {1,1,1,3,6,6,3};
__constant__ int c_cgPos[15] = {0,1,10,35,44,53,80,125,170,245,270,315,390,415,490};
__constant__ int c_cgL[15][3] = {{0,0,0},{0,1,1},{0,2,2},{1,0,1},{1,1,0},{1,1,1},{1,1,2},
  {1,2,1},{1,2,2},{2,0,2},{2,1,1},{2,1,2},{2,2,0},{2,2,1},{2,2,2}};

// ---------------- CG construction (replicates reference, fp64 core) ----------------
__device__ double dfact_(int n){ double r=1.0; for (int i=2;i<=n;++i) r*=(double)i; return r; }

__device__ double cg_c(int j1,int m1,int j2,int m2,int j3,int m3){
  if (m1+m2 != m3) return 0.0;
  double pref = sqrt((2.0*j3+1.0)*dfact_(j1+j2-j3)*dfact_(j1-j2+j3)*dfact_(-j1+j2+j3)/dfact_(j1+j2+j3+1));
  pref *= sqrt(dfact_(j1+m1)*dfact_(j1-m1)*dfact_(j2+m2)*dfact_(j2-m2)*dfact_(j3+m3)*dfact_(j3-m3));
  int kmin = 0;
  if (j2-j3-m1 > kmin) kmin = j2-j3-m1;
  if (j1-j3+m2 > kmin) kmin = j1-j3+m2;
  int kmax = j1+j2-j3;
  if (j1-m1 < kmax) kmax = j1-m1;
  if (j2+m2 < kmax) kmax = j2+m2;
  double s = 0.0;
  for (int k=kmin; k<=kmax; ++k){
    double dn = dfact_(k)*dfact_(j1+j2-j3-k)*dfact_(j1-m1-k)*dfact_(j2+m2-k)*dfact_(j3-j2+m1+k)*dfact_(j3-j1-m2+k);
    s += ((k&1)? -1.0 : 1.0)/dn;
  }
  return pref*s;
}

__device__ void qmat_f(int l, float Qr[5][5], float Qi[5][5]){
  for (int a=0;a<5;++a) for (int b=0;b<5;++b){ Qr[a][b]=0.f; Qi[a][b]=0.f; }
  Qr[l][l] = 1.f;
  const float s2 = 0.70710678118654752f;
  for (int m=1;m<=l;++m){
    float sg = (m&1)? -1.f : 1.f;
    Qr[l+m][l+m] = sg*s2;
    Qr[l+m][l-m] = s2;
    Qi[l-m][l-m] = s2;
    Qi[l-m][l+m] = -sg*s2;
  }
}

__global__ void cg_init_kernel(){
  int bid = blockIdx.x, t = threadIdx.x;
  int l1=c_cgL[bid][0], l2=c_cgL[bid][1], l3=c_cgL[bid][2];
  int n1=2*l1+1, n2=2*l2+1, n3=2*l3+1;
  __shared__ float Csh[5][5];
  __shared__ float Q1r[5][5],Q1i[5][5],Q2r[5][5],Q2i[5][5],Q3r[5][5],Q3i[5][5];
  __shared__ float Kr[125], Ki[125];
  __shared__ float s_scale;
  __shared__ int   s_useIm;
  if (t==0){ qmat_f(l1,Q1r,Q1i); qmat_f(l2,Q2r,Q2i); qmat_f(l3,Q3r,Q3i); }
  if (t < n1*n2){
    int a=t/n2, b=t%n2;
    int m1=a-l1, m2=b-l2, m3=m1+m2;
    Csh[a][b] = (m3>=-l3 && m3<=l3) ? (float)cg_c(l1,m1,l2,m2,l3,m3) : 0.f;
  }
  __syncthreads();
  int nel = n1*n2*n3;
  if (t < nel){
    int i=t/(n2*n3), j=(t/n3)%n2, k=t%n3;
    float sr=0.f, si=0.f;
    for (int a=0;a<n1;++a)
      for (int b=0;b<n2;++b){
        float Cv = Csh[a][b];
        if (Cv != 0.f){
          int cc = l3 + (a-l1) + (b-l2);
          float p1r=Q1r[i][a], p1i=-Q1i[i][a];
          float p2r=Q2r[j][b], p2i=-Q2i[j][b];
          float ar=p1r*p2r - p1i*p2i, ai=p1r*p2i + p1i*p2r;
          sr += (ar*Q3r[k][cc] - ai*Q3i[k][cc])*Cv;
          si += (ar*Q3i[k][cc] + ai*Q3r[k][cc])*Cv;
        }
      }
    Kr[t]=sr; Ki[t]=si;
  }
  __syncthreads();
  if (t==0){
    float mR=0.f, mI=0.f;
    for (int q=0;q<nel;++q){ mR=fmaxf(mR,fabsf(Kr[q])); mI=fmaxf(mI,fabsf(Ki[q])); }
    int useIm = (mI > mR);
    float nrm=0.f;
    for (int q=0;q<nel;++q){ float v = useIm ? -Ki[q] : Kr[q]; nrm += v*v; }
    s_scale = sqrtf((float)n3)*rsqrtf(nrm);
    s_useIm = useIm;
  }
  __syncthreads();
  if (t < nel){
    float v = s_useIm ? -Ki[t] : Kr[t];
    g_CG[c_cgPos[bid] + t] = v * s_scale;
  }
}

// ---------------- zero scratch accumulator ----------------
__global__ void zero_t_kernel(){
  int i = blockIdx.x*256 + threadIdx.x;
  if (i < NN*130) g_t[i] = 0.f;
}

// ---------------- radial MLP: w = silu(emb@W1)@W2 ----------------
template<int NOUT>
__global__ void radial_kernel(const float* __restrict__ evec,
                              const float* __restrict__ W1,    // (10,100)
                              const float* __restrict__ W2){   // (100,NOUT)
  __shared__ float sW1[1000];
  __shared__ float sHid[6400];
  __shared__ float sEmb[640];
  __shared__ float sR[64];
  int t = threadIdx.x;
  int e0 = blockIdx.x*64;
  for (int i=t;i<1000;i+=256) sW1[i]=W1[i];
  if (t < 64){
    int e = e0 + t;
    float vx=evec[3*e], vy=evec[3*e+1], vz=evec[3*e+2];
    sR[t] = sqrtf(vx*vx+vy*vy+vz*vz);
  }
  __syncthreads();
  const float step = 5.0f/11.0f;
  const float pref = 1.14136f * 7.3890560989306495f * 3.1622776601683795f;
  for (int i=t;i<640;i+=256){
    int el=i/10, b=i%10;
    float dd = (sR[el] - step*(float)(b+1))/step;
    float t1 = dd+1.f, t2 = 1.f-dd;
    float u1 = (t1>0.f)? expf(-1.f/t1) : 0.f;
    float u2 = (t2>0.f)? expf(-1.f/t2) : 0.f;
    sEmb[i] = pref*u1*u2;
  }
  __syncthreads();
  for (int i=t;i<6400;i+=256){
    int el=i/100, h=i%100;
    float a=0.f;
    #pragma unroll
    for (int b=0;b<10;++b) a += sEmb[el*10+b]*sW1[b*100+h];
    sHid[i] = a/(1.f+expf(-a));
  }
  __syncthreads();
  constexpr int NO8 = (NOUT+7)/8;
  for (int tile=t; tile<16*NO8; tile+=256){
    int eT = tile / NO8, oT = tile % NO8;
    int o0 = oT*8;
    float acc[4][8];
    #pragma unroll
    for (int a=0;a<4;++a)
      #pragma unroll
      for (int q=0;q<8;++q) acc[a][q]=0.f;
    const float* h0=&sHid[(eT*4+0)*100];
    const float* h1=&sHid[(eT*4+1)*100];
    const float* h2=&sHid[(eT*4+2)*100];
    const float* h3=&sHid[(eT*4+3)*100];
    #pragma unroll 2
    for (int h=0;h<100;++h){
      float f0=h0[h], f1=h1[h], f2=h2[h], f3=h3[h];
      #pragma unroll
      for (int q=0;q<8;++q){
        int o=o0+q;
        float wv = (o<NOUT)? W2[h*NOUT+o] : 0.f;
        acc[0][q]+=f0*wv; acc[1][q]+=f1*wv; acc[2][q]+=f2*wv; acc[3][q]+=f3*wv;
      }
    }
    #pragma unroll
    for (int a=0;a<4;++a){
      size_t e = (size_t)(e0 + eT*4 + a);
      #pragma unroll
      for (int q=0;q<8;++q){
        int o=o0+q;
        if (o<NOUT) g_w[e*NOUT + o] = acc[a][q];
      }
    }
  }
}

// ---------------- generic edge-conv (message + per-edge linear + scatter) ----------------
template<int VOUT, int NK>
__global__ void conv_edge_kernel(const float* __restrict__ evec,
                                 const int* __restrict__ src,
                                 const int* __restrict__ dst,
                                 const float* __restrict__ xin,
                                 int fsel, int fdim, int wtot,
                                 const float* __restrict__ lin,
                                 int tbl, int outOff){
  __shared__ float shY[9*256];
  int e = blockIdx.x*256 + threadIdx.x;
  if (e >= NE) return;
  const float* feats = (fsel==0)? xin : ((fsel==1)? g_h1 : g_h2);
  float vx=evec[3*e], vy=evec[3*e+1], vz=evec[3*e+2];
  float rn = rsqrtf(vx*vx+vy*vy+vz*vz);
  float X=vx*rn, Yc=vy*rn, Z=vz*rn;
  const float c3=1.7320508075688772f, c15=3.872983346207417f, c5=2.23606797749979f;
  int tid = threadIdx.x;
  shY[0*256+tid]=1.f;
  shY[1*256+tid]=c3*Yc; shY[2*256+tid]=c3*Z; shY[3*256+tid]=c3*X;
  shY[4*256+tid]=c15*X*Yc; shY[5*256+tid]=c15*Yc*Z;
  shY[6*256+tid]=0.5f*c5*(3.f*Z*Z-1.f);
  shY[7*256+tid]=c15*X*Z; shY[8*256+tid]=0.5f*c15*(X*X-Yc*Yc);
  int s = src[e], d = dst[e];
  float acc[VOUT][NK];
  #pragma unroll
  for (int v=0;v<VOUT;++v)
    #pragma unroll
    for (int k=0;k<NK;++k) acc[v][k]=0.f;
  int np = c_Tnum[tbl], pb = c_Toff[tbl];
  for (int pp=0; pp<np; ++pp){
    PathC P = c_P[pb+pp];
    int ni = 2*P.li+1;
    float B[5][NK];
    #pragma unroll
    for (int i=0;i<5;++i){
      if (i < ni){
        #pragma unroll
        for (int k=0;k<NK;++k){
          float b=0.f;
          #pragma unroll
          for (int j=0;j<5;++j)
            if (j < P.nj) b += shY[(P.yBase+j)*256+tid]*g_CG[P.cgOff + (i*P.nj+j)*NK + k];
          B[i][k]=b;
        }
      }
    }
    const float* frow = feats + (size_t)s*fdim + P.fOff;
    const float* wrow = g_w + (size_t)e*wtot + P.wOff;
    const float* lrow = lin + (size_t)P.ucat*VOUT;
    for (int u=0; u<P.mul; ++u){
      float pw = wrow[u];
      float m[NK];
      #pragma unroll
      for (int k=0;k<NK;++k){
        float a=0.f;
        #pragma unroll
        for (int i=0;i<5;++i)
          if (i < ni) a += frow[u*ni+i]*B[i][k];
        m[k]=a*pw;
      }
      const float* lr = lrow + u*VOUT;
      #pragma unroll
      for (int v=0;v<VOUT;++v){
        float lw = lr[v];
        #pragma unroll
        for (int k=0;k<NK;++k) acc[v][k] += lw*m[k];
      }
    }
  }
  float* ob = g_t + (size_t)d*130 + outOff;
  #pragma unroll
  for (int v=0;v<VOUT;++v)
    #pragma unroll
    for (int k=0;k<NK;++k) atomicAdd(&ob[v*NK+k], 0.25f*acc[v][k]);
}

// ---------------- node kernels ----------------
__global__ void post1_kernel(const float* __restrict__ x,
                             const float* __restrict__ sc1,    // (8,32)
                             const float* __restrict__ gw){    // (32,26)
  int n = blockIdx.x*128 + threadIdx.x;
  if (n >= NN) return;
  const float* tin = g_t + (size_t)n*130;
  float xr[8];
  #pragma unroll
  for (int u=0;u<8;++u) xr[u]=x[n*8+u];
  float s0[32];
  #pragma unroll
  for (int v=0;v<32;++v){
    float a = tin[v];
    #pragma unroll
    for (int u=0;u<8;++u) a += xr[u]*sc1[u*32+v];
    s0[v]=a;
  }
  float g[26];
  #pragma unroll
  for (int j=0;j<26;++j){
    float a=0.f;
    #pragma unroll
    for (int v=0;v<32;++v) a += s0[v]*gw[v*26+j];
    g[j]=1.f/(1.f+expf(-a));
  }
  float* ho = g_h1 + (size_t)n*130;
  #pragma unroll
  for (int v=0;v<32;++v) ho[v] = s0[v]/(1.f+expf(-s0[v]));
  #pragma unroll
  for (int v=0;v<16;++v)
    #pragma unroll
    for (int k=0;k<3;++k) ho[32+v*3+k] = tin[32+v*3+k]*g[v];
  #pragma unroll
  for (int v=0;v<10;++v)
    #pragma unroll
    for (int k=0;k<5;++k) ho[80+v*5+k] = tin[80+v*5+k]*g[16+v];
}

__global__ void post2_kernel(const float* __restrict__ sc0,   // (32,32)
                             const float* __restrict__ sc1m,  // (16,16)
                             const float* __restrict__ sc2m,  // (10,10)
                             const float* __restrict__ gw){   // (32,26)
  int n = blockIdx.x*128 + threadIdx.x;
  if (n >= NN) return;
  const float* tin = g_t + (size_t)n*130;
  const float* hp  = g_h1 + (size_t)n*130;
  float h0[32];
  #pragma unroll
  for (int u=0;u<32;++u) h0[u]=hp[u];
  float s0[32];
  #pragma unroll
  for (int v=0;v<32;++v){
    float a = tin[v];
    #pragma unroll
    for (int u=0;u<32;++u) a += h0[u]*sc0[u*32+v];
    s0[v]=a;
  }
  float g[26];
  #pragma unroll
  for (int j=0;j<26;++j){
    float a=0.f;
    #pragma unroll
    for (int v=0;v<32;++v) a += s0[v]*gw[v*26+j];
    g[j]=1.f/(1.f+expf(-a));
  }
  float* ho = g_h2 + (size_t)n*130;
  #pragma unroll
  for (int v=0;v<32;++v) ho[v] = s0[v]/(1.f+expf(-s0[v]));
  #pragma unroll
  for (int v=0;v<16;++v)
    #pragma unroll
    for (int k=0;k<3;++k){
      float a = tin[32+v*3+k];
      #pragma unroll
      for (int u=0;u<16;++u) a += hp[32+u*3+k]*sc1m[u*16+v];
      ho[32+v*3+k] = a*g[v];
    }
  #pragma unroll
  for (int v=0;v<10;++v)
    #pragma unroll
    for (int k=0;k<5;++k){
      float a = tin[80+v*5+k];
      #pragma unroll
      for (int u=0;u<10;++u) a += hp[80+u*5+k]*sc2m[u*10+v];
      ho[80+v*5+k] = a*g[16+v];
    }
}

__global__ void final_kernel(const float* __restrict__ sc3,   // (32,1)
                             float* __restrict__ out){
  int n = blockIdx.x*128 + threadIdx.x;
  if (n >= NN) return;
  float a = g_t[(size_t)n*130];
  const float* hp = g_h2 + (size_t)n*130;
  #pragma unroll
  for (int u=0;u<32;++u) a += hp[u]*sc3[u];
  out[n] = a;
}

// ---------------- launcher ----------------
extern "C" void kernel_launch(void* const* d_in, const int* in_sizes, int n_in,
                              void* d_out, int out_size){
  const float* x      = (const float*)d_in[0];
  const float* evec   = (const float*)d_in[1];
  const float* fc1w1  = (const float*)d_in[2];
  const float* fc1w2  = (const float*)d_in[3];
  const float* lin1l0 = (const float*)d_in[4];
  const float* lin1l1 = (const float*)d_in[5];
  const float* lin1l2 = (const float*)d_in[6];
  const float* sc1l0  = (const float*)d_in[7];
  const float* gate1  = (const float*)d_in[8];
  const float* fc2w1  = (const float*)d_in[9];
  const float* fc2w2  = (const float*)d_in[10];
  const float* lin2l0 = (const float*)d_in[11];
  const float* lin2l1 = (const float*)d_in[12];
  const float* lin2l2 = (const float*)d_in[13];
  const float* sc2l0  = (const float*)d_in[14];
  const float* sc2l1  = (const float*)d_in[15];
  const float* sc2l2  = (const float*)d_in[16];
  const float* gate2  = (const float*)d_in[17];
  const float* fc3w1  = (const float*)d_in[18];
  const float* fc3w2  = (const float*)d_in[19];
  const float* lin3l0 = (const float*)d_in[20];
  const float* sc3l0  = (const float*)d_in[21];
  const int*   esrc   = (const int*)d_in[22];
  const int*   edst   = (const int*)d_in[23];
  float* out = (float*)d_out;

  cg_init_kernel<<<15,128>>>();

  // ---- layer 1 ----
  zero_t_kernel<<<(NN*130+255)/256,256>>>();
  radial_kernel<24><<<NE/64,256>>>(evec, fc1w1, fc1w2);
  conv_edge_kernel<32,1><<<NE/256,256>>>(evec, esrc, edst, x, 0, 8, 24, lin1l0, 0, 0);
  conv_edge_kernel<16,3><<<NE/256,256>>>(evec, esrc, edst, x, 0, 8, 24, lin1l1, 1, 32);
  conv_edge_kernel<10,5><<<NE/256,256>>>(evec, esrc, edst, x, 0, 8, 24, lin1l2, 2, 80);
  post1_kernel<<<(NN+127)/128,128>>>(x, sc1l0, gate1);

  // ---- layer 2 ----
  zero_t_kernel<<<(NN*130+255)/256,256>>>();
  radial_kernel<252><<<NE/64,256>>>(evec, fc2w1, fc2w2);
  conv_edge_kernel<32,1><<<NE/256,256>>>(evec, esrc, edst, x, 1, 130, 252, lin2l0, 3, 0);
  conv_edge_kernel<16,3><<<NE/256,256>>>(evec, esrc, edst, x, 1, 130, 252, lin2l1, 4, 32);
  conv_edge_kernel<10,5><<<NE/256,256>>>(evec, esrc, edst, x, 1, 130, 252, lin2l2, 5, 80);
  post2_kernel<<<(NN+127)/128,128>>>(sc2l0, sc2l1, sc2l2, gate2);

  // ---- layer 3 ----
  zero_t_kernel<<<(NN*130+255)/256,256>>>();
  radial_kernel<58><<<NE/64,256>>>(evec, fc3w1, fc3w2);
  conv_edge_kernel<1,1><<<NE/256,256>>>(evec, esrc, edst, x, 2, 130, 58, lin3l0, 6, 0);
  final_kernel<<<(NN+127)/128,128>>>(sc3l0, out);
}

// round 9
// speedup vs baseline: 1.3745x; 1.3745x over previous
#include <cuda_runtime.h>
#include <math.h>

#define NN 10000
#define NE 160000

// ---------------- device scratch (no runtime allocation allowed) ----------------
__device__ float g_CG[615];
__device__ float g_w[(size_t)NE * 252];
__device__ float g_t[(size_t)NN * 130];
__device__ float g_h1[(size_t)NN * 130];
__device__ float g_h2[(size_t)NN * 130];

// ---------------- compile-time path tables ----------------
struct PathC { int li, fOff, mul, cgOff, yBase, nj, wOff, ucat; };
__constant__ PathC c_P[21] = {
  // T0..T2: conv1 lo=0,1,2 (input mul=8, li=0)
  {0,0,8,0,0,1,0,0},
  {0,0,8,1,1,3,8,0},
  {0,0,8,10,4,5,16,0},
  // T3: conv2 lo=0
  {0,0,32,0,0,1,0,0},{1,32,16,44,1,3,112,32},{2,80,10,390,4,5,222,48},
  // T4: conv2 lo=1
  {0,0,32,1,1,3,32,0},{1,32,16,35,0,1,96,32},{1,32,16,53,1,3,128,48},
  {1,32,16,125,4,5,160,64},{2,80,10,270,1,3,202,80},{2,80,10,415,4,5,232,90},
  // T5: conv2 lo=2
  {0,0,32,10,4,5,64,0},{1,32,16,80,1,3,144,32},{1,32,16,170,4,5,176,48},
  {2,80,10,245,0,1,192,64},{2,80,10,315,1,3,212,74},{2,80,10,490,4,5,242,84},
  // T6: conv3 lo=0
  {0,0,32,0,0,1,0,0},{1,32,16,44,1,3,32,32},{2,80,10,390,4,5,48,48}
};
__constant__ int c_Toff[7] = {0,1,2,3,6,12,18};
__constant__ int c_Tnum[7] = {1,1,1,3,6,6,3};
__constant__ int c_cgPos[15] = {0,1,10,35,44,53,80,125,170,245,270,315,390,415,490};
__constant__ int c_cgL[15][3] = {{0,0,0},{0,1,1},{0,2,2},{1,0,1},{1,1,0},{1,1,1},{1,1,2},
  {1,2,1},{1,2,2},{2,0,2},{2,1,1},{2,1,2},{2,2,0},{2,2,1},{2,2,2}};

// ---------------- CG construction (replicates reference, fp64 core) ----------------
__device__ double dfact_(int n){ double r=1.0; for (int i=2;i<=n;++i) r*=(double)i; return r; }

__device__ double cg_c(int j1,int m1,int j2,int m2,int j3,int m3){
  if (m1+m2 != m3) return 0.0;
  double pref = sqrt((2.0*j3+1.0)*dfact_(j1+j2-j3)*dfact_(j1-j2+j3)*dfact_(-j1+j2+j3)/dfact_(j1+j2+j3+1));
  pref *= sqrt(dfact_(j1+m1)*dfact_(j1-m1)*dfact_(j2+m2)*dfact_(j2-m2)*dfact_(j3+m3)*dfact_(j3-m3));
  int kmin = 0;
  if (j2-j3-m1 > kmin) kmin = j2-j3-m1;
  if (j1-j3+m2 > kmin) kmin = j1-j3+m2;
  int kmax = j1+j2-j3;
  if (j1-m1 < kmax) kmax = j1-m1;
  if (j2+m2 < kmax) kmax = j2+m2;
  double s = 0.0;
  for (int k=kmin; k<=kmax; ++k){
    double dn = dfact_(k)*dfact_(j1+j2-j3-k)*dfact_(j1-m1-k)*dfact_(j2+m2-k)*dfact_(j3-j2+m1+k)*dfact_(j3-j1-m2+k);
    s += ((k&1)? -1.0 : 1.0)/dn;
  }
  return pref*s;
}

__device__ void qmat_f(int l, float Qr[5][5], float Qi[5][5]){
  for (int a=0;a<5;++a) for (int b=0;b<5;++b){ Qr[a][b]=0.f; Qi[a][b]=0.f; }
  Qr[l][l] = 1.f;
  const float s2 = 0.70710678118654752f;
  for (int m=1;m<=l;++m){
    float sg = (m&1)? -1.f : 1.f;
    Qr[l+m][l+m] = sg*s2;
    Qr[l+m][l-m] = s2;
    Qi[l-m][l-m] = s2;
    Qi[l-m][l+m] = -sg*s2;
  }
}

__global__ void cg_init_kernel(){
  int bid = blockIdx.x, t = threadIdx.x;
  int l1=c_cgL[bid][0], l2=c_cgL[bid][1], l3=c_cgL[bid][2];
  int n1=2*l1+1, n2=2*l2+1, n3=2*l3+1;
  __shared__ float Csh[5][5];
  __shared__ float Q1r[5][5],Q1i[5][5],Q2r[5][5],Q2i[5][5],Q3r[5][5],Q3i[5][5];
  __shared__ float Kr[125], Ki[125];
  __shared__ float s_scale;
  __shared__ int   s_useIm;
  if (t==0){ qmat_f(l1,Q1r,Q1i); qmat_f(l2,Q2r,Q2i); qmat_f(l3,Q3r,Q3i); }
  if (t < n1*n2){
    int a=t/n2, b=t%n2;
    int m1=a-l1, m2=b-l2, m3=m1+m2;
    Csh[a][b] = (m3>=-l3 && m3<=l3) ? (float)cg_c(l1,m1,l2,m2,l3,m3) : 0.f;
  }
  __syncthreads();
  int nel = n1*n2*n3;
  if (t < nel){
    int i=t/(n2*n3), j=(t/n3)%n2, k=t%n3;
    float sr=0.f, si=0.f;
    for (int a=0;a<n1;++a)
      for (int b=0;b<n2;++b){
        float Cv = Csh[a][b];
        if (Cv != 0.f){
          int cc = l3 + (a-l1) + (b-l2);
          float p1r=Q1r[i][a], p1i=-Q1i[i][a];
          float p2r=Q2r[j][b], p2i=-Q2i[j][b];
          float ar=p1r*p2r - p1i*p2i, ai=p1r*p2i + p1i*p2r;
          sr += (ar*Q3r[k][cc] - ai*Q3i[k][cc])*Cv;
          si += (ar*Q3i[k][cc] + ai*Q3r[k][cc])*Cv;
        }
      }
    Kr[t]=sr; Ki[t]=si;
  }
  __syncthreads();
  if (t==0){
    float mR=0.f, mI=0.f;
    for (int q=0;q<nel;++q){ mR=fmaxf(mR,fabsf(Kr[q])); mI=fmaxf(mI,fabsf(Ki[q])); }
    int useIm = (mI > mR);
    float nrm=0.f;
    for (int q=0;q<nel;++q){ float v = useIm ? -Ki[q] : Kr[q]; nrm += v*v; }
    s_scale = sqrtf((float)n3)*rsqrtf(nrm);
    s_useIm = useIm;
  }
  __syncthreads();
  if (t < nel){
    float v = s_useIm ? -Ki[t] : Kr[t];
    g_CG[c_cgPos[bid] + t] = v * s_scale;
  }
}

// ---------------- zero scratch accumulator ----------------
__global__ void zero_t_kernel(){
  int i = blockIdx.x*256 + threadIdx.x;
  if (i < NN*130) g_t[i] = 0.f;
}

// ---------------- radial MLP: w = silu(emb@W1)@W2 ----------------
// Phase 2 redesigned: warp owns 8 edges; outputs tiled o = q*32 + lane so W2
// loads are lane-coalesced (1 L1 wavefront vs 8) and g_w writes are coalesced.
template<int NOUT>
__global__ void radial_kernel(const float* __restrict__ evec,
                              const float* __restrict__ W1,    // (10,100)
                              const float* __restrict__ W2){   // (100,NOUT)
  __shared__ float sW1[1000];
  __shared__ float sHid[6400];
  __shared__ float sEmb[640];
  __shared__ float sR[64];
  int t = threadIdx.x;
  int e0 = blockIdx.x*64;
  for (int i=t;i<1000;i+=256) sW1[i]=W1[i];
  if (t < 64){
    int e = e0 + t;
    float vx=evec[3*e], vy=evec[3*e+1], vz=evec[3*e+2];
    sR[t] = sqrtf(vx*vx+vy*vy+vz*vz);
  }
  __syncthreads();
  const float step = 5.0f/11.0f;
  const float pref = 1.14136f * 7.3890560989306495f * 3.1622776601683795f;
  for (int i=t;i<640;i+=256){
    int el=i/10, b=i%10;
    float dd = (sR[el] - step*(float)(b+1))/step;
    float t1 = dd+1.f, t2 = 1.f-dd;
    float u1 = (t1>0.f)? expf(-1.f/t1) : 0.f;
    float u2 = (t2>0.f)? expf(-1.f/t2) : 0.f;
    sEmb[i] = pref*u1*u2;
  }
  __syncthreads();
  for (int i=t;i<6400;i+=256){
    int el=i/100, h=i%100;
    float a=0.f;
    #pragma unroll
    for (int b=0;b<10;++b) a += sEmb[el*10+b]*sW1[b*100+h];
    sHid[i] = a/(1.f+expf(-a));
  }
  __syncthreads();
  constexpr int NQ = (NOUT+31)/32;
  int warp = t>>5, lane = t&31;
  int eb = warp*8;                    // 8 edges per warp, 8 warps = 64 edges
  float acc[8][NQ];
  #pragma unroll
  for (int a=0;a<8;++a)
    #pragma unroll
    for (int q=0;q<NQ;++q) acc[a][q]=0.f;
  #pragma unroll 2
  for (int h=0;h<100;++h){
    float wv[NQ];
    #pragma unroll
    for (int q=0;q<NQ;++q){
      int o = q*32 + lane;
      wv[q] = (o<NOUT)? W2[h*NOUT+o] : 0.f;
    }
    #pragma unroll
    for (int a=0;a<8;++a){
      float f = sHid[(eb+a)*100 + h];   // broadcast LDS
      #pragma unroll
      for (int q=0;q<NQ;++q) acc[a][q] += f*wv[q];
    }
  }
  #pragma unroll
  for (int a=0;a<8;++a){
    size_t e = (size_t)(e0 + eb + a);
    #pragma unroll
    for (int q=0;q<NQ;++q){
      int o = q*32 + lane;
      if (o<NOUT) g_w[e*NOUT + o] = acc[a][q];
    }
  }
}

// ---------------- generic edge-conv (message + per-edge linear + scatter) ----------------
template<int VOUT, int NK>
__global__ void conv_edge_kernel(const float* __restrict__ evec,
                                 const int* __restrict__ src,
                                 const int* __restrict__ dst,
                                 const float* __restrict__ xin,
                                 int fsel, int fdim, int wtot,
                                 const float* __restrict__ lin,
                                 int tbl, int outOff){
  __shared__ float shY[9*256];
  int e = blockIdx.x*256 + threadIdx.x;
  if (e >= NE) return;
  const float* feats = (fsel==0)? xin : ((fsel==1)? g_h1 : g_h2);
  float vx=evec[3*e], vy=evec[3*e+1], vz=evec[3*e+2];
  float rn = rsqrtf(vx*vx+vy*vy+vz*vz);
  float X=vx*rn, Yc=vy*rn, Z=vz*rn;
  const float c3=1.7320508075688772f, c15=3.872983346207417f, c5=2.23606797749979f;
  int tid = threadIdx.x;
  shY[0*256+tid]=1.f;
  shY[1*256+tid]=c3*Yc; shY[2*256+tid]=c3*Z; shY[3*256+tid]=c3*X;
  shY[4*256+tid]=c15*X*Yc; shY[5*256+tid]=c15*Yc*Z;
  shY[6*256+tid]=0.5f*c5*(3.f*Z*Z-1.f);
  shY[7*256+tid]=c15*X*Z; shY[8*256+tid]=0.5f*c15*(X*X-Yc*Yc);
  int s = src[e], d = dst[e];
  float acc[VOUT][NK];
  #pragma unroll
  for (int v=0;v<VOUT;++v)
    #pragma unroll
    for (int k=0;k<NK;++k) acc[v][k]=0.f;
  int np = c_Tnum[tbl], pb = c_Toff[tbl];
  for (int pp=0; pp<np; ++pp){
    PathC P = c_P[pb+pp];
    int ni = 2*P.li+1;
    float B[5][NK];
    #pragma unroll
    for (int i=0;i<5;++i){
      if (i < ni){
        #pragma unroll
        for (int k=0;k<NK;++k){
          float b=0.f;
          #pragma unroll
          for (int j=0;j<5;++j)
            if (j < P.nj) b += shY[(P.yBase+j)*256+tid]*g_CG[P.cgOff + (i*P.nj+j)*NK + k];
          B[i][k]=b;
        }
      }
    }
    const float* frow = feats + (size_t)s*fdim + P.fOff;
    const float* wrow = g_w + (size_t)e*wtot + P.wOff;
    const float* lrow = lin + (size_t)P.ucat*VOUT;
    for (int u=0; u<P.mul; ++u){
      float pw = wrow[u];
      float m[NK];
      #pragma unroll
      for (int k=0;k<NK;++k){
        float a=0.f;
        #pragma unroll
        for (int i=0;i<5;++i)
          if (i < ni) a += frow[u*ni+i]*B[i][k];
        m[k]=a*pw;
      }
      const float* lr = lrow + u*VOUT;
      #pragma unroll
      for (int v=0;v<VOUT;++v){
        float lw = lr[v];
        #pragma unroll
        for (int k=0;k<NK;++k) acc[v][k] += lw*m[k];
      }
    }
  }
  float* ob = g_t + (size_t)d*130 + outOff;
  #pragma unroll
  for (int v=0;v<VOUT;++v)
    #pragma unroll
    for (int k=0;k<NK;++k) atomicAdd(&ob[v*NK+k], 0.25f*acc[v][k]);
}

// ---------------- node kernels ----------------
__global__ void post1_kernel(const float* __restrict__ x,
                             const float* __restrict__ sc1,    // (8,32)
                             const float* __restrict__ gw){    // (32,26)
  int n = blockIdx.x*128 + threadIdx.x;
  if (n >= NN) return;
  const float* tin = g_t + (size_t)n*130;
  float xr[8];
  #pragma unroll
  for (int u=0;u<8;++u) xr[u]=x[n*8+u];
  float s0[32];
  #pragma unroll
  for (int v=0;v<32;++v){
    float a = tin[v];
    #pragma unroll
    for (int u=0;u<8;++u) a += xr[u]*sc1[u*32+v];
    s0[v]=a;
  }
  float g[26];
  #pragma unroll
  for (int j=0;j<26;++j){
    float a=0.f;
    #pragma unroll
    for (int v=0;v<32;++v) a += s0[v]*gw[v*26+j];
    g[j]=1.f/(1.f+expf(-a));
  }
  float* ho = g_h1 + (size_t)n*130;
  #pragma unroll
  for (int v=0;v<32;++v) ho[v] = s0[v]/(1.f+expf(-s0[v]));
  #pragma unroll
  for (int v=0;v<16;++v)
    #pragma unroll
    for (int k=0;k<3;++k) ho[32+v*3+k] = tin[32+v*3+k]*g[v];
  #pragma unroll
  for (int v=0;v<10;++v)
    #pragma unroll
    for (int k=0;k<5;++k) ho[80+v*5+k] = tin[80+v*5+k]*g[16+v];
}

__global__ void post2_kernel(const float* __restrict__ sc0,   // (32,32)
                             const float* __restrict__ sc1m,  // (16,16)
                             const float* __restrict__ sc2m,  // (10,10)
                             const float* __restrict__ gw){   // (32,26)
  int n = blockIdx.x*128 + threadIdx.x;
  if (n >= NN) return;
  const float* tin = g_t + (size_t)n*130;
  const float* hp  = g_h1 + (size_t)n*130;
  float h0[32];
  #pragma unroll
  for (int u=0;u<32;++u) h0[u]=hp[u];
  float s0[32];
  #pragma unroll
  for (int v=0;v<32;++v){
    float a = tin[v];
    #pragma unroll
    for (int u=0;u<32;++u) a += h0[u]*sc0[u*32+v];
    s0[v]=a;
  }
  float g[26];
  #pragma unroll
  for (int j=0;j<26;++j){
    float a=0.f;
    #pragma unroll
    for (int v=0;v<32;++v) a += s0[v]*gw[v*26+j];
    g[j]=1.f/(1.f+expf(-a));
  }
  float* ho = g_h2 + (size_t)n*130;
  #pragma unroll
  for (int v=0;v<32;++v) ho[v] = s0[v]/(1.f+expf(-s0[v]));
  #pragma unroll
  for (int v=0;v<16;++v)
    #pragma unroll
    for (int k=0;k<3;++k){
      float a = tin[32+v*3+k];
      #pragma unroll
      for (int u=0;u<16;++u) a += hp[32+u*3+k]*sc1m[u*16+v];
      ho[32+v*3+k] = a*g[v];
    }
  #pragma unroll
  for (int v=0;v<10;++v)
    #pragma unroll
    for (int k=0;k<5;++k){
      float a = tin[80+v*5+k];
      #pragma unroll
      for (int u=0;u<10;++u) a += hp[80+u*5+k]*sc2m[u*10+v];
      ho[80+v*5+k] = a*g[16+v];
    }
}

__global__ void final_kernel(const float* __restrict__ sc3,   // (32,1)
                             float* __restrict__ out){
  int n = blockIdx.x*128 + threadIdx.x;
  if (n >= NN) return;
  float a = g_t[(size_t)n*130];
  const float* hp = g_h2 + (size_t)n*130;
  #pragma unroll
  for (int u=0;u<32;++u) a += hp[u]*sc3[u];
  out[n] = a;
}

// ---------------- launcher ----------------
extern "C" void kernel_launch(void* const* d_in, const int* in_sizes, int n_in,
                              void* d_out, int out_size){
  const float* x      = (const float*)d_in[0];
  const float* evec   = (const float*)d_in[1];
  const float* fc1w1  = (const float*)d_in[2];
  const float* fc1w2  = (const float*)d_in[3];
  const float* lin1l0 = (const float*)d_in[4];
  const float* lin1l1 = (const float*)d_in[5];
  const float* lin1l2 = (const float*)d_in[6];
  const float* sc1l0  = (const float*)d_in[7];
  const float* gate1  = (const float*)d_in[8];
  const float* fc2w1  = (const float*)d_in[9];
  const float* fc2w2  = (const float*)d_in[10];
  const float* lin2l0 = (const float*)d_in[11];
  const float* lin2l1 = (const float*)d_in[12];
  const float* lin2l2 = (const float*)d_in[13];
  const float* sc2l0  = (const float*)d_in[14];
  const float* sc2l1  = (const float*)d_in[15];
  const float* sc2l2  = (const float*)d_in[16];
  const float* gate2  = (const float*)d_in[17];
  const float* fc3w1  = (const float*)d_in[18];
  const float* fc3w2  = (const float*)d_in[19];
  const float* lin3l0 = (const float*)d_in[20];
  const float* sc3l0  = (const float*)d_in[21];
  const int*   esrc   = (const int*)d_in[22];
  const int*   edst   = (const int*)d_in[23];
  float* out = (float*)d_out;

  cg_init_kernel<<<15,128>>>();

  // ---- layer 1 ----
  zero_t_kernel<<<(NN*130+255)/256,256>>>();
  radial_kernel<24><<<NE/64,256>>>(evec, fc1w1, fc1w2);
  conv_edge_kernel<32,1><<<NE/256,256>>>(evec, esrc, edst, x, 0, 8, 24, lin1l0, 0, 0);
  conv_edge_kernel<16,3><<<NE/256,256>>>(evec, esrc, edst, x, 0, 8, 24, lin1l1, 1, 32);
  conv_edge_kernel<10,5><<<NE/256,256>>>(evec, esrc, edst, x, 0, 8, 24, lin1l2, 2, 80);
  post1_kernel<<<(NN+127)/128,128>>>(x, sc1l0, gate1);

  // ---- layer 2 ----
  zero_t_kernel<<<(NN*130+255)/256,256>>>();
  radial_kernel<252><<<NE/64,256>>>(evec, fc2w1, fc2w2);
  conv_edge_kernel<32,1><<<NE/256,256>>>(evec, esrc, edst, x, 1, 130, 252, lin2l0, 3, 0);
  conv_edge_kernel<16,3><<<NE/256,256>>>(evec, esrc, edst, x, 1, 130, 252, lin2l1, 4, 32);
  conv_edge_kernel<10,5><<<NE/256,256>>>(evec, esrc, edst, x, 1, 130, 252, lin2l2, 5, 80);
  post2_kernel<<<(NN+127)/128,128>>>(sc2l0, sc2l1, sc2l2, gate2);

  // ---- layer 3 ----
  zero_t_kernel<<<(NN*130+255)/256,256>>>();
  radial_kernel<58><<<NE/64,256>>>(evec, fc3w1, fc3w2);
  conv_edge_kernel<1,1><<<NE/256,256>>>(evec, esrc, edst, x, 2, 130, 58, lin3l0, 6, 0);
  final_kernel<<<(NN+127)/128,128>>>(sc3l0, out);
}

// round 14
// speedup vs baseline: 1.8729x; 1.3627x over previous
#include <cuda_runtime.h>
#include <math.h>

#define NN 10000
#define NE 160000
#define WSTR 256

// ---------------- device scratch (no runtime allocation allowed) ----------------
__device__ float g_CG[615];
__device__ float g_w[(size_t)NE * WSTR];
__device__ float g_t[(size_t)NN * 130];
__device__ float g_h1[(size_t)NN * 130];
__device__ float g_h2[(size_t)NN * 130];

// ---------------- CG init tables ----------------
__constant__ int c_cgPos[15] = {0,1,10,35,44,53,80,125,170,245,270,315,390,415,490};
__constant__ int c_cgL[15][3] = {{0,0,0},{0,1,1},{0,2,2},{1,0,1},{1,1,0},{1,1,1},{1,1,2},
  {1,2,1},{1,2,2},{2,0,2},{2,1,1},{2,1,2},{2,2,0},{2,2,1},{2,2,2}};

// ---------------- compile-time group descriptors (device-safe accessors) ----------------
#define GARR(name, N, ...) \
  __device__ static constexpr int name(int p){ const int a[N]={__VA_ARGS__}; return a[p]; }

struct G1L0 { static constexpr int np=1, vout=32, nk=1, oo=0;
  GARR(li,1, 0) GARR(fo,1, 0) GARR(mul,1, 8) GARR(cg,1, 0)
  GARR(yb,1, 0) GARR(nj,1, 1) GARR(wo,1, 0) GARR(uc,1, 0) };
struct G1L1 { static constexpr int np=1, vout=16, nk=3, oo=32;
  GARR(li,1, 0) GARR(fo,1, 0) GARR(mul,1, 8) GARR(cg,1, 1)
  GARR(yb,1, 1) GARR(nj,1, 3) GARR(wo,1, 8) GARR(uc,1, 0) };
struct G1L2 { static constexpr int np=1, vout=10, nk=5, oo=80;
  GARR(li,1, 0) GARR(fo,1, 0) GARR(mul,1, 8) GARR(cg,1, 10)
  GARR(yb,1, 4) GARR(nj,1, 5) GARR(wo,1, 16) GARR(uc,1, 0) };

struct G2L0 { static constexpr int np=3, vout=32, nk=1, oo=0;
  GARR(li,3, 0,1,2) GARR(fo,3, 0,32,80) GARR(mul,3, 32,16,10)
  GARR(cg,3, 0,44,390) GARR(yb,3, 0,1,4) GARR(nj,3, 1,3,5)
  GARR(wo,3, 0,112,222) GARR(uc,3, 0,32,48) };
struct G2L1 { static constexpr int np=6, vout=16, nk=3, oo=32;
  GARR(li,6, 0,1,1,1,2,2) GARR(fo,6, 0,32,32,32,80,80)
  GARR(mul,6, 32,16,16,16,10,10) GARR(cg,6, 1,35,53,125,270,415)
  GARR(yb,6, 1,0,1,4,1,4) GARR(nj,6, 3,1,3,5,3,5)
  GARR(wo,6, 32,96,128,160,202,232) GARR(uc,6, 0,32,48,64,80,90) };
struct G2L2 { static constexpr int np=6, vout=10, nk=5, oo=80;
  GARR(li,6, 0,1,1,2,2,2) GARR(fo,6, 0,32,32,80,80,80)
  GARR(mul,6, 32,16,16,10,10,10) GARR(cg,6, 10,80,170,245,315,490)
  GARR(yb,6, 4,1,4,0,1,4) GARR(nj,6, 5,3,5,1,3,5)
  GARR(wo,6, 64,144,176,192,212,242) GARR(uc,6, 0,32,48,64,74,84) };

struct G3L0 { static constexpr int np=3, vout=1, nk=1, oo=0;
  GARR(li,3, 0,1,2) GARR(fo,3, 0,32,80) GARR(mul,3, 32,16,10)
  GARR(cg,3, 0,44,390) GARR(yb,3, 0,1,4) GARR(nj,3, 1,3,5)
  GARR(wo,3, 0,32,48) GARR(uc,3, 0,32,48) };

// ---------------- CG construction (replicates reference, fp64 core) ----------------
__device__ double dfact_(int n){ double r=1.0; for (int i=2;i<=n;++i) r*=(double)i; return r; }

__device__ double cg_c(int j1,int m1,int j2,int m2,int j3,int m3){
  if (m1+m2 != m3) return 0.0;
  double pref = sqrt((2.0*j3+1.0)*dfact_(j1+j2-j3)*dfact_(j1-j2+j3)*dfact_(-j1+j2+j3)/dfact_(j1+j2+j3+1));
  pref *= sqrt(dfact_(j1+m1)*dfact_(j1-m1)*dfact_(j2+m2)*dfact_(j2-m2)*dfact_(j3+m3)*dfact_(j3-m3));
  int kmin = 0;
  if (j2-j3-m1 > kmin) kmin = j2-j3-m1;
  if (j1-j3+m2 > kmin) kmin = j1-j3+m2;
  int kmax = j1+j2-j3;
  if (j1-m1 < kmax) kmax = j1-m1;
  if (j2+m2 < kmax) kmax = j2+m2;
  double s = 0.0;
  for (int k=kmin; k<=kmax; ++k){
    double dn = dfact_(k)*dfact_(j1+j2-j3-k)*dfact_(j1-m1-k)*dfact_(j2+m2-k)*dfact_(j3-j2+m1+k)*dfact_(j3-j1-m2+k);
    s += ((k&1)? -1.0 : 1.0)/dn;
  }
  return pref*s;
}

__device__ void qmat_f(int l, float Qr[5][5], float Qi[5][5]){
  for (int a=0;a<5;++a) for (int b=0;b<5;++b){ Qr[a][b]=0.f; Qi[a][b]=0.f; }
  Qr[l][l] = 1.f;
  const float s2 = 0.70710678118654752f;
  for (int m=1;m<=l;++m){
    float sg = (m&1)? -1.f : 1.f;
    Qr[l+m][l+m] = sg*s2;
    Qr[l+m][l-m] = s2;
    Qi[l-m][l-m] = s2;
    Qi[l-m][l+m] = -sg*s2;
  }
}

__global__ void cg_init_kernel(){
  int bid = blockIdx.x, t = threadIdx.x;
  int l1=c_cgL[bid][0], l2=c_cgL[bid][1], l3=c_cgL[bid][2];
  int n1=2*l1+1, n2=2*l2+1, n3=2*l3+1;
  __shared__ float Csh[5][5];
  __shared__ float Q1r[5][5],Q1i[5][5],Q2r[5][5],Q2i[5][5],Q3r[5][5],Q3i[5][5];
  __shared__ float Kr[125], Ki[125];
  __shared__ float s_scale;
  __shared__ int   s_useIm;
  if (t==0){ qmat_f(l1,Q1r,Q1i); qmat_f(l2,Q2r,Q2i); qmat_f(l3,Q3r,Q3i); }
  if (t < n1*n2){
    int a=t/n2, b=t%n2;
    int m1=a-l1, m2=b-l2, m3=m1+m2;
    Csh[a][b] = (m3>=-l3 && m3<=l3) ? (float)cg_c(l1,m1,l2,m2,l3,m3) : 0.f;
  }
  __syncthreads();
  int nel = n1*n2*n3;
  if (t < nel){
    int i=t/(n2*n3), j=(t/n3)%n2, k=t%n3;
    float sr=0.f, si=0.f;
    for (int a=0;a<n1;++a)
      for (int b=0;b<n2;++b){
        float Cv = Csh[a][b];
        if (Cv != 0.f){
          int cc = l3 + (a-l1) + (b-l2);
          float p1r=Q1r[i][a], p1i=-Q1i[i][a];
          float p2r=Q2r[j][b], p2i=-Q2i[j][b];
          float ar=p1r*p2r - p1i*p2i, ai=p1r*p2i + p1i*p2r;
          sr += (ar*Q3r[k][cc] - ai*Q3i[k][cc])*Cv;
          si += (ar*Q3i[k][cc] + ai*Q3r[k][cc])*Cv;
        }
      }
    Kr[t]=sr; Ki[t]=si;
  }
  __syncthreads();
  if (t==0){
    float mR=0.f, mI=0.f;
    for (int q=0;q<nel;++q){ mR=fmaxf(mR,fabsf(Kr[q])); mI=fmaxf(mI,fabsf(Ki[q])); }
    int useIm = (mI > mR);
    float nrm=0.f;
    for (int q=0;q<nel;++q){ float v = useIm ? -Ki[q] : Kr[q]; nrm += v*v; }
    s_scale = sqrtf((float)n3)*rsqrtf(nrm);
    s_useIm = useIm;
  }
  __syncthreads();
  if (t < nel){
    float v = s_useIm ? -Ki[t] : Kr[t];
    g_CG[c_cgPos[bid] + t] = v * s_scale;
  }
}

// ---------------- zero scratch accumulator ----------------
__global__ void zero_t_kernel(){
  int i = blockIdx.x*256 + threadIdx.x;
  if (i < NN*130) g_t[i] = 0.f;
}

// ---------------- radial MLP: w = silu(emb@W1)@W2 ----------------
template<int NOUT>
__global__ void radial_kernel(const float* __restrict__ evec,
                              const float* __restrict__ W1,    // (10,100)
                              const float* __restrict__ W2){   // (100,NOUT)
  __shared__ float sW1[1000];
  __shared__ float sHid[6400];
  __shared__ float sEmb[640];
  __shared__ float sR[64];
  int t = threadIdx.x;
  int e0 = blockIdx.x*64;
  for (int i=t;i<1000;i+=256) sW1[i]=W1[i];
  if (t < 64){
    int e = e0 + t;
    float vx=evec[3*e], vy=evec[3*e+1], vz=evec[3*e+2];
    sR[t] = sqrtf(vx*vx+vy*vy+vz*vz);
  }
  __syncthreads();
  const float step = 5.0f/11.0f;
  const float pref = 1.14136f * 7.3890560989306495f * 3.1622776601683795f;
  for (int i=t;i<640;i+=256){
    int el=i/10, b=i%10;
    float dd = (sR[el] - step*(float)(b+1))/step;
    float t1 = dd+1.f, t2 = 1.f-dd;
    float u1 = (t1>0.f)? expf(-1.f/t1) : 0.f;
    float u2 = (t2>0.f)? expf(-1.f/t2) : 0.f;
    sEmb[i] = pref*u1*u2;
  }
  __syncthreads();
  for (int i=t;i<6400;i+=256){
    int el=i/100, h=i%100;
    float a=0.f;
    #pragma unroll
    for (int b=0;b<10;++b) a += sEmb[el*10+b]*sW1[b*100+h];
    sHid[i] = a/(1.f+expf(-a));
  }
  __syncthreads();
  constexpr int NQ = (NOUT+31)/32;
  int warp = t>>5, lane = t&31;
  int eb = warp*8;
  float acc[8][NQ];
  #pragma unroll
  for (int a=0;a<8;++a)
    #pragma unroll
    for (int q=0;q<NQ;++q) acc[a][q]=0.f;
  #pragma unroll 2
  for (int h=0;h<100;++h){
    float wv[NQ];
    #pragma unroll
    for (int q=0;q<NQ;++q){
      int o = q*32 + lane;
      wv[q] = (o<NOUT)? W2[h*NOUT+o] : 0.f;
    }
    #pragma unroll
    for (int a=0;a<8;++a){
      float f = sHid[(eb+a)*100 + h];
      #pragma unroll
      for (int q=0;q<NQ;++q) acc[a][q] += f*wv[q];
    }
  }
  #pragma unroll
  for (int a=0;a<8;++a){
    size_t e = (size_t)(e0 + eb + a);
    #pragma unroll
    for (int q=0;q<NQ;++q){
      int o = q*32 + lane;
      if (o<NOUT) g_w[e*WSTR + o] = acc[a][q];
    }
  }
}

// ---------------- fully-unrolled per-group tensor product + linear + scatter ----------------
template<class G>
__device__ __forceinline__ void run_group(const float* __restrict__ sFrow,
                                          const float (&Y)[9],
                                          const float* __restrict__ sCG,
                                          const float* __restrict__ wrow,
                                          const float* __restrict__ lin,
                                          float* __restrict__ obase){
  constexpr int VOUT = G::vout, NK = G::nk;
  float acc[VOUT][NK];
  #pragma unroll
  for (int v=0;v<VOUT;++v)
    #pragma unroll
    for (int k=0;k<NK;++k) acc[v][k]=0.f;
  #pragma unroll
  for (int p=0;p<G::np;++p){
    const int ni = 2*G::li(p)+1;
    float B[5][NK];
    #pragma unroll
    for (int i=0;i<5;++i){
      if (i < ni){
        #pragma unroll
        for (int k=0;k<NK;++k){
          float b=0.f;
          #pragma unroll
          for (int j=0;j<5;++j)
            if (j < G::nj(p)) b += Y[G::yb(p)+j]*sCG[G::cg(p)+(i*G::nj(p)+j)*NK+k];
          B[i][k]=b;
        }
      }
    }
    const float* f = sFrow + G::fo(p);
    const float* w = wrow + G::wo(p);
    const float* L = lin + G::uc(p)*VOUT;
    #pragma unroll 4
    for (int u=0;u<G::mul(p);++u){
      float pw = w[u];
      float m[NK];
      #pragma unroll
      for (int k=0;k<NK;++k){
        float a=0.f;
        #pragma unroll
        for (int i=0;i<5;++i)
          if (i < ni) a += f[u*ni+i]*B[i][k];
        m[k]=a*pw;
      }
      #pragma unroll
      for (int v=0;v<VOUT;++v){
        float lw = L[u*VOUT+v];
        #pragma unroll
        for (int k=0;k<NK;++k) acc[v][k] += lw*m[k];
      }
    }
  }
  #pragma unroll
  for (int v=0;v<VOUT;++v)
    #pragma unroll
    for (int k=0;k<NK;++k) atomicAdd(&obase[v*NK+k], 0.25f*acc[v][k]);
}

// ---------------- merged conv kernel: 64 edges/block, f staged in shared ----------------
// fsel resolves the feature pointer IN DEVICE CODE (g_h1/g_h2 are __device__
// globals whose address cannot be taken from the host).
template<class GA, class GB, class GC, int NG, int FDIM, int FSTR>
__global__ void conv_merged_kernel(const float* __restrict__ evec,
                                   const int* __restrict__ src,
                                   const int* __restrict__ dst,
                                   const float* __restrict__ xin,
                                   int fsel,
                                   const float* __restrict__ linA,
                                   const float* __restrict__ linB,
                                   const float* __restrict__ linC){
  __shared__ float sF[64*FSTR];
  __shared__ float sCG[615];
  __shared__ int sSrc[64];
  int t = threadIdx.x;           // 64 threads
  int e0 = blockIdx.x*64;
  const float* feats = (fsel==0)? xin : ((fsel==1)? g_h1 : g_h2);
  for (int i=t;i<615;i+=64) sCG[i]=g_CG[i];
  sSrc[t]=src[e0+t];
  __syncthreads();
  for (int idx=t; idx<64*FDIM; idx+=64){
    int el=idx/FDIM, c=idx-el*FDIM;
    sF[el*FSTR+c] = feats[(size_t)sSrc[el]*FDIM + c];
  }
  __syncthreads();
  int e = e0 + t;
  float vx=evec[3*e], vy=evec[3*e+1], vz=evec[3*e+2];
  float rn = rsqrtf(vx*vx+vy*vy+vz*vz);
  float X=vx*rn, Yv=vy*rn, Z=vz*rn;
  const float c3=1.7320508075688772f, c15=3.872983346207417f, c5=2.23606797749979f;
  float Y[9] = {1.f, c3*Yv, c3*Z, c3*X,
                c15*X*Yv, c15*Yv*Z, 0.5f*c5*(3.f*Z*Z-1.f), c15*X*Z, 0.5f*c15*(X*X-Yv*Yv)};
  const float* wrow = g_w + (size_t)e*WSTR;
  const float* myF  = sF + t*FSTR;
  int d = dst[e];
  float* tb = g_t + (size_t)d*130;
  run_group<GA>(myF, Y, sCG, wrow, linA, tb + GA::oo);
  if constexpr (NG > 1) run_group<GB>(myF, Y, sCG, wrow, linB, tb + GB::oo);
  if constexpr (NG > 2) run_group<GC>(myF, Y, sCG, wrow, linC, tb + GC::oo);
}

// ---------------- node kernels ----------------
__global__ void post1_kernel(const float* __restrict__ x,
                             const float* __restrict__ sc1,    // (8,32)
                             const float* __restrict__ gw){    // (32,26)
  int n = blockIdx.x*128 + threadIdx.x;
  if (n >= NN) return;
  const float* tin = g_t + (size_t)n*130;
  float xr[8];
  #pragma unroll
  for (int u=0;u<8;++u) xr[u]=x[n*8+u];
  float s0[32];
  #pragma unroll
  for (int v=0;v<32;++v){
    float a = tin[v];
    #pragma unroll
    for (int u=0;u<8;++u) a += xr[u]*sc1[u*32+v];
    s0[v]=a;
  }
  float g[26];
  #pragma unroll
  for (int j=0;j<26;++j){
    float a=0.f;
    #pragma unroll
    for (int v=0;v<32;++v) a += s0[v]*gw[v*26+j];
    g[j]=1.f/(1.f+expf(-a));
  }
  float* ho = g_h1 + (size_t)n*130;
  #pragma unroll
  for (int v=0;v<32;++v) ho[v] = s0[v]/(1.f+expf(-s0[v]));
  #pragma unroll
  for (int v=0;v<16;++v)
    #pragma unroll
    for (int k=0;k<3;++k) ho[32+v*3+k] = tin[32+v*3+k]*g[v];
  #pragma unroll
  for (int v=0;v<10;++v)
    #pragma unroll
    for (int k=0;k<5;++k) ho[80+v*5+k] = tin[80+v*5+k]*g[16+v];
}

__global__ void post2_kernel(const float* __restrict__ sc0,   // (32,32)
                             const float* __restrict__ sc1m,  // (16,16)
                             const float* __restrict__ sc2m,  // (10,10)
                             const float* __restrict__ gw){   // (32,26)
  int n = blockIdx.x*128 + threadIdx.x;
  if (n >= NN) return;
  const float* tin = g_t + (size_t)n*130;
  const float* hp  = g_h1 + (size_t)n*130;
  float h0[32];
  #pragma unroll
  for (int u=0;u<32;++u) h0[u]=hp[u];
  float s0[32];
  #pragma unroll
  for (int v=0;v<32;++v){
    float a = tin[v];
    #pragma unroll
    for (int u=0;u<32;++u) a += h0[u]*sc0[u*32+v];
    s0[v]=a;
  }
  float g[26];
  #pragma unroll
  for (int j=0;j<26;++j){
    float a=0.f;
    #pragma unroll
    for (int v=0;v<32;++v) a += s0[v]*gw[v*26+j];
    g[j]=1.f/(1.f+expf(-a));
  }
  float* ho = g_h2 + (size_t)n*130;
  #pragma unroll
  for (int v=0;v<32;++v) ho[v] = s0[v]/(1.f+expf(-s0[v]));
  #pragma unroll
  for (int v=0;v<16;++v)
    #pragma unroll
    for (int k=0;k<3;++k){
      float a = tin[32+v*3+k];
      #pragma unroll
      for (int u=0;u<16;++u) a += hp[32+u*3+k]*sc1m[u*16+v];
      ho[32+v*3+k] = a*g[v];
    }
  #pragma unroll
  for (int v=0;v<10;++v)
    #pragma unroll
    for (int k=0;k<5;++k){
      float a = tin[80+v*5+k];
      #pragma unroll
      for (int u=0;u<10;++u) a += hp[80+u*5+k]*sc2m[u*10+v];
      ho[80+v*5+k] = a*g[16+v];
    }
}

__global__ void final_kernel(const float* __restrict__ sc3,   // (32,1)
                             float* __restrict__ out){
  int n = blockIdx.x*128 + threadIdx.x;
  if (n >= NN) return;
  float a = g_t[(size_t)n*130];
  const float* hp = g_h2 + (size_t)n*130;
  #pragma unroll
  for (int u=0;u<32;++u) a += hp[u]*sc3[u];
  out[n] = a;
}

// ---------------- launcher ----------------
extern "C" void kernel_launch(void* const* d_in, const int* in_sizes, int n_in,
                              void* d_out, int out_size){
  const float* x      = (const float*)d_in[0];
  const float* evec   = (const float*)d_in[1];
  const float* fc1w1  = (const float*)d_in[2];
  const float* fc1w2  = (const float*)d_in[3];
  const float* lin1l0 = (const float*)d_in[4];
  const float* lin1l1 = (const float*)d_in[5];
  const float* lin1l2 = (const float*)d_in[6];
  const float* sc1l0  = (const float*)d_in[7];
  const float* gate1  = (const float*)d_in[8];
  const float* fc2w1  = (const float*)d_in[9];
  const float* fc2w2  = (const float*)d_in[10];
  const float* lin2l0 = (const float*)d_in[11];
  const float* lin2l1 = (const float*)d_in[12];
  const float* lin2l2 = (const float*)d_in[13];
  const float* sc2l0  = (const float*)d_in[14];
  const float* sc2l1  = (const float*)d_in[15];
  const float* sc2l2  = (const float*)d_in[16];
  const float* gate2  = (const float*)d_in[17];
  const float* fc3w1  = (const float*)d_in[18];
  const float* fc3w2  = (const float*)d_in[19];
  const float* lin3l0 = (const float*)d_in[20];
  const float* sc3l0  = (const float*)d_in[21];
  const int*   esrc   = (const int*)d_in[22];
  const int*   edst   = (const int*)d_in[23];
  float* out = (float*)d_out;

  cg_init_kernel<<<15,128>>>();

  // ---- layer 1 ----
  zero_t_kernel<<<(NN*130+255)/256,256>>>();
  radial_kernel<24><<<NE/64,256>>>(evec, fc1w1, fc1w2);
  conv_merged_kernel<G1L0,G1L1,G1L2,3,8,9><<<NE/64,64>>>(
      evec, esrc, edst, x, 0, lin1l0, lin1l1, lin1l2);
  post1_kernel<<<(NN+127)/128,128>>>(x, sc1l0, gate1);

  // ---- layer 2 ----
  zero_t_kernel<<<(NN*130+255)/256,256>>>();
  radial_kernel<252><<<NE/64,256>>>(evec, fc2w1, fc2w2);
  conv_merged_kernel<G2L0,G2L1,G2L2,3,130,131><<<NE/64,64>>>(
      evec, esrc, edst, x, 1, lin2l0, lin2l1, lin2l2);
  post2_kernel<<<(NN+127)/128,128>>>(sc2l0, sc2l1, sc2l2, gate2);

  // ---- layer 3 ----
  zero_t_kernel<<<(NN*130+255)/256,256>>>();
  radial_kernel<58><<<NE/64,256>>>(evec, fc3w1, fc3w2);
  conv_merged_kernel<G3L0,G3L0,G3L0,1,130,131><<<NE/64,64>>>(
      evec, esrc, edst, x, 2, lin3l0, lin3l0, lin3l0);
  final_kernel<<<(NN+127)/128,128>>>(sc3l0, out);
}

// round 15
// speedup vs baseline: 2.0609x; 1.1004x over previous
#include <cuda_runtime.h>
#include <math.h>

#define NN 10000
#define NE 160000
#define WSTR 256
#define TSTR 132   // g_t row stride (floats); 132*4=528 bytes, 16B-aligned

// ---------------- device scratch (no runtime allocation allowed) ----------------
__device__ float g_CG[615];
__device__ float g_w[(size_t)NE * WSTR];
__device__ __align__(16) float g_t[(size_t)NN * TSTR];
__device__ float g_h1[(size_t)NN * 130];
__device__ float g_h2[(size_t)NN * 130];

// ---------------- CG init tables ----------------
__constant__ int c_cgPos[15] = {0,1,10,35,44,53,80,125,170,245,270,315,390,415,490};
__constant__ int c_cgL[15][3] = {{0,0,0},{0,1,1},{0,2,2},{1,0,1},{1,1,0},{1,1,1},{1,1,2},
  {1,2,1},{1,2,2},{2,0,2},{2,1,1},{2,1,2},{2,2,0},{2,2,1},{2,2,2}};

// ---------------- compile-time group descriptors (device-safe accessors) ----------------
#define GARR(name, N, ...) \
  __device__ static constexpr int name(int p){ const int a[N]={__VA_ARGS__}; return a[p]; }

struct G1L0 { static constexpr int np=1, vout=32, nk=1, oo=0;
  GARR(li,1, 0) GARR(fo,1, 0) GARR(mul,1, 8) GARR(cg,1, 0)
  GARR(yb,1, 0) GARR(nj,1, 1) GARR(wo,1, 0) GARR(uc,1, 0) };
struct G1L1 { static constexpr int np=1, vout=16, nk=3, oo=32;
  GARR(li,1, 0) GARR(fo,1, 0) GARR(mul,1, 8) GARR(cg,1, 1)
  GARR(yb,1, 1) GARR(nj,1, 3) GARR(wo,1, 8) GARR(uc,1, 0) };
struct G1L2 { static constexpr int np=1, vout=10, nk=5, oo=80;
  GARR(li,1, 0) GARR(fo,1, 0) GARR(mul,1, 8) GARR(cg,1, 10)
  GARR(yb,1, 4) GARR(nj,1, 5) GARR(wo,1, 16) GARR(uc,1, 0) };

struct G2L0 { static constexpr int np=3, vout=32, nk=1, oo=0;
  GARR(li,3, 0,1,2) GARR(fo,3, 0,32,80) GARR(mul,3, 32,16,10)
  GARR(cg,3, 0,44,390) GARR(yb,3, 0,1,4) GARR(nj,3, 1,3,5)
  GARR(wo,3, 0,112,222) GARR(uc,3, 0,32,48) };
struct G2L1 { static constexpr int np=6, vout=16, nk=3, oo=32;
  GARR(li,6, 0,1,1,1,2,2) GARR(fo,6, 0,32,32,32,80,80)
  GARR(mul,6, 32,16,16,16,10,10) GARR(cg,6, 1,35,53,125,270,415)
  GARR(yb,6, 1,0,1,4,1,4) GARR(nj,6, 3,1,3,5,3,5)
  GARR(wo,6, 32,96,128,160,202,232) GARR(uc,6, 0,32,48,64,80,90) };
struct G2L2 { static constexpr int np=6, vout=10, nk=5, oo=80;
  GARR(li,6, 0,1,1,2,2,2) GARR(fo,6, 0,32,32,80,80,80)
  GARR(mul,6, 32,16,16,10,10,10) GARR(cg,6, 10,80,170,245,315,490)
  GARR(yb,6, 4,1,4,0,1,4) GARR(nj,6, 5,3,5,1,3,5)
  GARR(wo,6, 64,144,176,192,212,242) GARR(uc,6, 0,32,48,64,74,84) };

struct G3L0 { static constexpr int np=3, vout=1, nk=1, oo=0;
  GARR(li,3, 0,1,2) GARR(fo,3, 0,32,80) GARR(mul,3, 32,16,10)
  GARR(cg,3, 0,44,390) GARR(yb,3, 0,1,4) GARR(nj,3, 1,3,5)
  GARR(wo,3, 0,32,48) GARR(uc,3, 0,32,48) };

// ---------------- vectorized global reductions (sm_90+) ----------------
__device__ __forceinline__ void red4(float* p, float a, float b, float c, float d){
  asm volatile("red.global.add.v4.f32 [%0], {%1,%2,%3,%4};"
               :: "l"(p), "f"(a), "f"(b), "f"(c), "f"(d) : "memory");
}
__device__ __forceinline__ void red2(float* p, float a, float b){
  asm volatile("red.global.add.v2.f32 [%0], {%1,%2};"
               :: "l"(p), "f"(a), "f"(b) : "memory");
}

// ---------------- CG construction (replicates reference, fp64 core) ----------------
__device__ double dfact_(int n){ double r=1.0; for (int i=2;i<=n;++i) r*=(double)i; return r; }

__device__ double cg_c(int j1,int m1,int j2,int m2,int j3,int m3){
  if (m1+m2 != m3) return 0.0;
  double pref = sqrt((2.0*j3+1.0)*dfact_(j1+j2-j3)*dfact_(j1-j2+j3)*dfact_(-j1+j2+j3)/dfact_(j1+j2+j3+1));
  pref *= sqrt(dfact_(j1+m1)*dfact_(j1-m1)*dfact_(j2+m2)*dfact_(j2-m2)*dfact_(j3+m3)*dfact_(j3-m3));
  int kmin = 0;
  if (j2-j3-m1 > kmin) kmin = j2-j3-m1;
  if (j1-j3+m2 > kmin) kmin = j1-j3+m2;
  int kmax = j1+j2-j3;
  if (j1-m1 < kmax) kmax = j1-m1;
  if (j2+m2 < kmax) kmax = j2+m2;
  double s = 0.0;
  for (int k=kmin; k<=kmax; ++k){
    double dn = dfact_(k)*dfact_(j1+j2-j3-k)*dfact_(j1-m1-k)*dfact_(j2+m2-k)*dfact_(j3-j2+m1+k)*dfact_(j3-j1-m2+k);
    s += ((k&1)? -1.0 : 1.0)/dn;
  }
  return pref*s;
}

__device__ void qmat_f(int l, float Qr[5][5], float Qi[5][5]){
  for (int a=0;a<5;++a) for (int b=0;b<5;++b){ Qr[a][b]=0.f; Qi[a][b]=0.f; }
  Qr[l][l] = 1.f;
  const float s2 = 0.70710678118654752f;
  for (int m=1;m<=l;++m){
    float sg = (m&1)? -1.f : 1.f;
    Qr[l+m][l+m] = sg*s2;
    Qr[l+m][l-m] = s2;
    Qi[l-m][l-m] = s2;
    Qi[l-m][l+m] = -sg*s2;
  }
}

__global__ void cg_init_kernel(){
  int bid = blockIdx.x, t = threadIdx.x;
  int l1=c_cgL[bid][0], l2=c_cgL[bid][1], l3=c_cgL[bid][2];
  int n1=2*l1+1, n2=2*l2+1, n3=2*l3+1;
  __shared__ float Csh[5][5];
  __shared__ float Q1r[5][5],Q1i[5][5],Q2r[5][5],Q2i[5][5],Q3r[5][5],Q3i[5][5];
  __shared__ float Kr[125], Ki[125];
  __shared__ float s_scale;
  __shared__ int   s_useIm;
  if (t==0){ qmat_f(l1,Q1r,Q1i); qmat_f(l2,Q2r,Q2i); qmat_f(l3,Q3r,Q3i); }
  if (t < n1*n2){
    int a=t/n2, b=t%n2;
    int m1=a-l1, m2=b-l2, m3=m1+m2;
    Csh[a][b] = (m3>=-l3 && m3<=l3) ? (float)cg_c(l1,m1,l2,m2,l3,m3) : 0.f;
  }
  __syncthreads();
  int nel = n1*n2*n3;
  if (t < nel){
    int i=t/(n2*n3), j=(t/n3)%n2, k=t%n3;
    float sr=0.f, si=0.f;
    for (int a=0;a<n1;++a)
      for (int b=0;b<n2;++b){
        float Cv = Csh[a][b];
        if (Cv != 0.f){
          int cc = l3 + (a-l1) + (b-l2);
          float p1r=Q1r[i][a], p1i=-Q1i[i][a];
          float p2r=Q2r[j][b], p2i=-Q2i[j][b];
          float ar=p1r*p2r - p1i*p2i, ai=p1r*p2i + p1i*p2r;
          sr += (ar*Q3r[k][cc] - ai*Q3i[k][cc])*Cv;
          si += (ar*Q3i[k][cc] + ai*Q3r[k][cc])*Cv;
        }
      }
    Kr[t]=sr; Ki[t]=si;
  }
  __syncthreads();
  if (t==0){
    float mR=0.f, mI=0.f;
    for (int q=0;q<nel;++q){ mR=fmaxf(mR,fabsf(Kr[q])); mI=fmaxf(mI,fabsf(Ki[q])); }
    int useIm = (mI > mR);
    float nrm=0.f;
    for (int q=0;q<nel;++q){ float v = useIm ? -Ki[q] : Kr[q]; nrm += v*v; }
    s_scale = sqrtf((float)n3)*rsqrtf(nrm);
    s_useIm = useIm;
  }
  __syncthreads();
  if (t < nel){
    float v = s_useIm ? -Ki[t] : Kr[t];
    g_CG[c_cgPos[bid] + t] = v * s_scale;
  }
}

// ---------------- zero scratch accumulator ----------------
__global__ void zero_t_kernel(){
  int i = blockIdx.x*256 + threadIdx.x;
  if (i < NN*TSTR) g_t[i] = 0.f;
}

// ---------------- radial MLP: w = silu(emb@W1)@W2 ----------------
template<int NOUT>
__global__ void radial_kernel(const float* __restrict__ evec,
                              const float* __restrict__ W1,    // (10,100)
                              const float* __restrict__ W2){   // (100,NOUT)
  __shared__ float sW1[1000];
  __shared__ float sHid[6400];
  __shared__ float sEmb[640];
  __shared__ float sR[64];
  int t = threadIdx.x;
  int e0 = blockIdx.x*64;
  for (int i=t;i<1000;i+=256) sW1[i]=W1[i];
  if (t < 64){
    int e = e0 + t;
    float vx=evec[3*e], vy=evec[3*e+1], vz=evec[3*e+2];
    sR[t] = sqrtf(vx*vx+vy*vy+vz*vz);
  }
  __syncthreads();
  const float step = 5.0f/11.0f;
  const float pref = 1.14136f * 7.3890560989306495f * 3.1622776601683795f;
  for (int i=t;i<640;i+=256){
    int el=i/10, b=i%10;
    float dd = (sR[el] - step*(float)(b+1))/step;
    float t1 = dd+1.f, t2 = 1.f-dd;
    float u1 = (t1>0.f)? expf(-1.f/t1) : 0.f;
    float u2 = (t2>0.f)? expf(-1.f/t2) : 0.f;
    sEmb[i] = pref*u1*u2;
  }
  __syncthreads();
  for (int i=t;i<6400;i+=256){
    int el=i/100, h=i%100;
    float a=0.f;
    #pragma unroll
    for (int b=0;b<10;++b) a += sEmb[el*10+b]*sW1[b*100+h];
    sHid[i] = a/(1.f+expf(-a));
  }
  __syncthreads();
  constexpr int NQ = (NOUT+31)/32;
  int warp = t>>5, lane = t&31;
  int eb = warp*8;
  float acc[8][NQ];
  #pragma unroll
  for (int a=0;a<8;++a)
    #pragma unroll
    for (int q=0;q<NQ;++q) acc[a][q]=0.f;
  #pragma unroll 2
  for (int h=0;h<100;++h){
    float wv[NQ];
    #pragma unroll
    for (int q=0;q<NQ;++q){
      int o = q*32 + lane;
      wv[q] = (o<NOUT)? W2[h*NOUT+o] : 0.f;
    }
    #pragma unroll
    for (int a=0;a<8;++a){
      float f = sHid[(eb+a)*100 + h];
      #pragma unroll
      for (int q=0;q<NQ;++q) acc[a][q] += f*wv[q];
    }
  }
  #pragma unroll
  for (int a=0;a<8;++a){
    size_t e = (size_t)(e0 + eb + a);
    #pragma unroll
    for (int q=0;q<NQ;++q){
      int o = q*32 + lane;
      if (o<NOUT) g_w[e*WSTR + o] = acc[a][q];
    }
  }
}

// ---------------- fully-unrolled per-group tensor product + linear + scatter ----------------
template<class G>
__device__ __forceinline__ void run_group(const float* __restrict__ sFrow,
                                          const float (&Y)[9],
                                          const float* __restrict__ sCG,
                                          const float* __restrict__ wrow,
                                          const float* __restrict__ lin,
                                          float* __restrict__ obase){
  constexpr int VOUT = G::vout, NK = G::nk;
  float acc[VOUT][NK];
  #pragma unroll
  for (int v=0;v<VOUT;++v)
    #pragma unroll
    for (int k=0;k<NK;++k) acc[v][k]=0.f;
  #pragma unroll
  for (int p=0;p<G::np;++p){
    const int ni = 2*G::li(p)+1;
    float B[5][NK];
    #pragma unroll
    for (int i=0;i<5;++i){
      if (i < ni){
        #pragma unroll
        for (int k=0;k<NK;++k){
          float b=0.f;
          #pragma unroll
          for (int j=0;j<5;++j)
            if (j < G::nj(p)) b += Y[G::yb(p)+j]*sCG[G::cg(p)+(i*G::nj(p)+j)*NK+k];
          B[i][k]=b;
        }
      }
    }
    const float* f = sFrow + G::fo(p);
    const float* w = wrow + G::wo(p);
    const float* L = lin + G::uc(p)*VOUT;
    #pragma unroll 4
    for (int u=0;u<G::mul(p);++u){
      float pw = w[u];
      float m[NK];
      #pragma unroll
      for (int k=0;k<NK;++k){
        float a=0.f;
        #pragma unroll
        for (int i=0;i<5;++i)
          if (i < ni) a += f[u*ni+i]*B[i][k];
        m[k]=a*pw;
      }
      #pragma unroll
      for (int v=0;v<VOUT;++v){
        float lw = L[u*VOUT+v];
        #pragma unroll
        for (int k=0;k<NK;++k) acc[v][k] += lw*m[k];
      }
    }
  }
  // flush with vectorized global reductions (obase is 16B-aligned for all groups)
  constexpr int TOT = VOUT*NK;
  float* fl = &acc[0][0];
  if constexpr (TOT >= 4){
    #pragma unroll
    for (int i=0; i+3<TOT; i+=4)
      red4(obase+i, 0.25f*fl[i], 0.25f*fl[i+1], 0.25f*fl[i+2], 0.25f*fl[i+3]);
  }
  if constexpr ((TOT & 3) >= 2){
    constexpr int b = TOT & ~3;
    red2(obase+b, 0.25f*fl[b], 0.25f*fl[b+1]);
  }
  if constexpr (TOT & 1){
    atomicAdd(obase + (TOT-1), 0.25f*fl[TOT-1]);
  }
}

// ---------------- merged conv kernel: 64 edges/block, f staged in shared ----------------
template<class GA, class GB, class GC, int NG, int FDIM, int FSTR>
__global__ void conv_merged_kernel(const float* __restrict__ evec,
                                   const int* __restrict__ src,
                                   const int* __restrict__ dst,
                                   const float* __restrict__ xin,
                                   int fsel,
                                   const float* __restrict__ linA,
                                   const float* __restrict__ linB,
                                   const float* __restrict__ linC){
  __shared__ float sF[64*FSTR];
  __shared__ float sCG[615];
  __shared__ int sSrc[64];
  int t = threadIdx.x;           // 64 threads
  int e0 = blockIdx.x*64;
  const float* feats = (fsel==0)? xin : ((fsel==1)? g_h1 : g_h2);
  for (int i=t;i<615;i+=64) sCG[i]=g_CG[i];
  sSrc[t]=src[e0+t];
  __syncthreads();
  for (int idx=t; idx<64*FDIM; idx+=64){
    int el=idx/FDIM, c=idx-el*FDIM;
    sF[el*FSTR+c] = feats[(size_t)sSrc[el]*FDIM + c];
  }
  __syncthreads();
  int e = e0 + t;
  float vx=evec[3*e], vy=evec[3*e+1], vz=evec[3*e+2];
  float rn = rsqrtf(vx*vx+vy*vy+vz*vz);
  float X=vx*rn, Yv=vy*rn, Z=vz*rn;
  const float c3=1.7320508075688772f, c15=3.872983346207417f, c5=2.23606797749979f;
  float Y[9] = {1.f, c3*Yv, c3*Z, c3*X,
                c15*X*Yv, c15*Yv*Z, 0.5f*c5*(3.f*Z*Z-1.f), c15*X*Z, 0.5f*c15*(X*X-Yv*Yv)};
  const float* wrow = g_w + (size_t)e*WSTR;
  const float* myF  = sF + t*FSTR;
  int d = dst[e];
  float* tb = g_t + (size_t)d*TSTR;
  run_group<GA>(myF, Y, sCG, wrow, linA, tb + GA::oo);
  if constexpr (NG > 1) run_group<GB>(myF, Y, sCG, wrow, linB, tb + GB::oo);
  if constexpr (NG > 2) run_group<GC>(myF, Y, sCG, wrow, linC, tb + GC::oo);
}

// ---------------- node kernels ----------------
__global__ void post1_kernel(const float* __restrict__ x,
                             const float* __restrict__ sc1,    // (8,32)
                             const float* __restrict__ gw){    // (32,26)
  int n = blockIdx.x*128 + threadIdx.x;
  if (n >= NN) return;
  const float* tin = g_t + (size_t)n*TSTR;
  float xr[8];
  #pragma unroll
  for (int u=0;u<8;++u) xr[u]=x[n*8+u];
  float s0[32];
  #pragma unroll
  for (int v=0;v<32;++v){
    float a = tin[v];
    #pragma unroll
    for (int u=0;u<8;++u) a += xr[u]*sc1[u*32+v];
    s0[v]=a;
  }
  float g[26];
  #pragma unroll
  for (int j=0;j<26;++j){
    float a=0.f;
    #pragma unroll
    for (int v=0;v<32;++v) a += s0[v]*gw[v*26+j];
    g[j]=1.f/(1.f+expf(-a));
  }
  float* ho = g_h1 + (size_t)n*130;
  #pragma unroll
  for (int v=0;v<32;++v) ho[v] = s0[v]/(1.f+expf(-s0[v]));
  #pragma unroll
  for (int v=0;v<16;++v)
    #pragma unroll
    for (int k=0;k<3;++k) ho[32+v*3+k] = tin[32+v*3+k]*g[v];
  #pragma unroll
  for (int v=0;v<10;++v)
    #pragma unroll
    for (int k=0;k<5;++k) ho[80+v*5+k] = tin[80+v*5+k]*g[16+v];
}

__global__ void post2_kernel(const float* __restrict__ sc0,   // (32,32)
                             const float* __restrict__ sc1m,  // (16,16)
                             const float* __restrict__ sc2m,  // (10,10)
                             const float* __restrict__ gw){   // (32,26)
  int n = blockIdx.x*128 + threadIdx.x;
  if (n >= NN) return;
  const float* tin = g_t + (size_t)n*TSTR;
  const float* hp  = g_h1 + (size_t)n*130;
  float h0[32];
  #pragma unroll
  for (int u=0;u<32;++u) h0[u]=hp[u];
  float s0[32];
  #pragma unroll
  for (int v=0;v<32;++v){
    float a = tin[v];
    #pragma unroll
    for (int u=0;u<32;++u) a += h0[u]*sc0[u*32+v];
    s0[v]=a;
  }
  float g[26];
  #pragma unroll
  for (int j=0;j<26;++j){
    float a=0.f;
    #pragma unroll
    for (int v=0;v<32;++v) a += s0[v]*gw[v*26+j];
    g[j]=1.f/(1.f+expf(-a));
  }
  float* ho = g_h2 + (size_t)n*130;
  #pragma unroll
  for (int v=0;v<32;++v) ho[v] = s0[v]/(1.f+expf(-s0[v]));
  #pragma unroll
  for (int v=0;v<16;++v)
    #pragma unroll
    for (int k=0;k<3;++k){
      float a = tin[32+v*3+k];
      #pragma unroll
      for (int u=0;u<16;++u) a += hp[32+u*3+k]*sc1m[u*16+v];
      ho[32+v*3+k] = a*g[v];
    }
  #pragma unroll
  for (int v=0;v<10;++v)
    #pragma unroll
    for (int k=0;k<5;++k){
      float a = tin[80+v*5+k];
      #pragma unroll
      for (int u=0;u<10;++u) a += hp[80+u*5+k]*sc2m[u*10+v];
      ho[80+v*5+k] = a*g[16+v];
    }
}

__global__ void final_kernel(const float* __restrict__ sc3,   // (32,1)
                             float* __restrict__ out){
  int n = blockIdx.x*128 + threadIdx.x;
  if (n >= NN) return;
  float a = g_t[(size_t)n*TSTR];
  const float* hp = g_h2 + (size_t)n*130;
  #pragma unroll
  for (int u=0;u<32;++u) a += hp[u]*sc3[u];
  out[n] = a;
}

// ---------------- launcher ----------------
extern "C" void kernel_launch(void* const* d_in, const int* in_sizes, int n_in,
                              void* d_out, int out_size){
  const float* x      = (const float*)d_in[0];
  const float* evec   = (const float*)d_in[1];
  const float* fc1w1  = (const float*)d_in[2];
  const float* fc1w2  = (const float*)d_in[3];
  const float* lin1l0 = (const float*)d_in[4];
  const float* lin1l1 = (const float*)d_in[5];
  const float* lin1l2 = (const float*)d_in[6];
  const float* sc1l0  = (const float*)d_in[7];
  const float* gate1  = (const float*)d_in[8];
  const float* fc2w1  = (const float*)d_in[9];
  const float* fc2w2  = (const float*)d_in[10];
  const float* lin2l0 = (const float*)d_in[11];
  const float* lin2l1 = (const float*)d_in[12];
  const float* lin2l2 = (const float*)d_in[13];
  const float* sc2l0  = (const float*)d_in[14];
  const float* sc2l1  = (const float*)d_in[15];
  const float* sc2l2  = (const float*)d_in[16];
  const float* gate2  = (const float*)d_in[17];
  const float* fc3w1  = (const float*)d_in[18];
  const float* fc3w2  = (const float*)d_in[19];
  const float* lin3l0 = (const float*)d_in[20];
  const float* sc3l0  = (const float*)d_in[21];
  const int*   esrc   = (const int*)d_in[22];
  const int*   edst   = (const int*)d_in[23];
  float* out = (float*)d_out;

  cg_init_kernel<<<15,128>>>();

  // ---- layer 1 ----
  zero_t_kernel<<<(NN*TSTR+255)/256,256>>>();
  radial_kernel<24><<<NE/64,256>>>(evec, fc1w1, fc1w2);
  conv_merged_kernel<G1L0,G1L1,G1L2,3,8,9><<<NE/64,64>>>(
      evec, esrc, edst, x, 0, lin1l0, lin1l1, lin1l2);
  post1_kernel<<<(NN+127)/128,128>>>(x, sc1l0, gate1);

  // ---- layer 2 ----
  zero_t_kernel<<<(NN*TSTR+255)/256,256>>>();
  radial_kernel<252><<<NE/64,256>>>(evec, fc2w1, fc2w2);
  conv_merged_kernel<G2L0,G2L1,G2L2,3,130,131><<<NE/64,64>>>(
      evec, esrc, edst, x, 1, lin2l0, lin2l1, lin2l2);
  post2_kernel<<<(NN+127)/128,128>>>(sc2l0, sc2l1, sc2l2, gate2);

  // ---- layer 3 ----
  zero_t_kernel<<<(NN*TSTR+255)/256,256>>>();
  radial_kernel<58><<<NE/64,256>>>(evec, fc3w1, fc3w2);
  conv_merged_kernel<G3L0,G3L0,G3L0,1,130,131><<<NE/64,64>>>(
      evec, esrc, edst, x, 2, lin3l0, lin3l0, lin3l0);
  final_kernel<<<(NN+127)/128,128>>>(sc3l0, out);
}

// round 16
// speedup vs baseline: 2.8058x; 1.3614x over previous
#include <cuda_runtime.h>
#include <math.h>

#define NN 10000
#define NE 160000
#define WSTR 256
#define TSTR 132   // g_t row stride (floats); 132*4=528 bytes, 16B-aligned
#define NTAB 8192
#define RMAX 5.0f

// ---------------- device scratch (no runtime allocation allowed) ----------------
__device__ float g_CG[615];
__device__ float g_w[(size_t)NE * WSTR];
__device__ __align__(16) float g_t[(size_t)NN * TSTR];
__device__ float g_h1[(size_t)NN * 130];
__device__ float g_h2[(size_t)NN * 130];
__device__ float g_tab[3][(size_t)NTAB * WSTR];   // radial weight tables per conv

// ---------------- CG init tables ----------------
__constant__ int c_cgPos[15] = {0,1,10,35,44,53,80,125,170,245,270,315,390,415,490};
__constant__ int c_cgL[15][3] = {{0,0,0},{0,1,1},{0,2,2},{1,0,1},{1,1,0},{1,1,1},{1,1,2},
  {1,2,1},{1,2,2},{2,0,2},{2,1,1},{2,1,2},{2,2,0},{2,2,1},{2,2,2}};

// ---------------- compile-time group descriptors (device-safe accessors) ----------------
#define GARR(name, N, ...) \
  __device__ static constexpr int name(int p){ const int a[N]={__VA_ARGS__}; return a[p]; }

struct G1L0 { static constexpr int np=1, vout=32, nk=1, oo=0;
  GARR(li,1, 0) GARR(fo,1, 0) GARR(mul,1, 8) GARR(cg,1, 0)
  GARR(yb,1, 0) GARR(nj,1, 1) GARR(wo,1, 0) GARR(uc,1, 0) };
struct G1L1 { static constexpr int np=1, vout=16, nk=3, oo=32;
  GARR(li,1, 0) GARR(fo,1, 0) GARR(mul,1, 8) GARR(cg,1, 1)
  GARR(yb,1, 1) GARR(nj,1, 3) GARR(wo,1, 8) GARR(uc,1, 0) };
struct G1L2 { static constexpr int np=1, vout=10, nk=5, oo=80;
  GARR(li,1, 0) GARR(fo,1, 0) GARR(mul,1, 8) GARR(cg,1, 10)
  GARR(yb,1, 4) GARR(nj,1, 5) GARR(wo,1, 16) GARR(uc,1, 0) };

struct G2L0 { static constexpr int np=3, vout=32, nk=1, oo=0;
  GARR(li,3, 0,1,2) GARR(fo,3, 0,32,80) GARR(mul,3, 32,16,10)
  GARR(cg,3, 0,44,390) GARR(yb,3, 0,1,4) GARR(nj,3, 1,3,5)
  GARR(wo,3, 0,112,222) GARR(uc,3, 0,32,48) };
struct G2L1 { static constexpr int np=6, vout=16, nk=3, oo=32;
  GARR(li,6, 0,1,1,1,2,2) GARR(fo,6, 0,32,32,32,80,80)
  GARR(mul,6, 32,16,16,16,10,10) GARR(cg,6, 1,35,53,125,270,415)
  GARR(yb,6, 1,0,1,4,1,4) GARR(nj,6, 3,1,3,5,3,5)
  GARR(wo,6, 32,96,128,160,202,232) GARR(uc,6, 0,32,48,64,80,90) };
struct G2L2 { static constexpr int np=6, vout=10, nk=5, oo=80;
  GARR(li,6, 0,1,1,2,2,2) GARR(fo,6, 0,32,32,80,80,80)
  GARR(mul,6, 32,16,16,10,10,10) GARR(cg,6, 10,80,170,245,315,490)
  GARR(yb,6, 4,1,4,0,1,4) GARR(nj,6, 5,3,5,1,3,5)
  GARR(wo,6, 64,144,176,192,212,242) GARR(uc,6, 0,32,48,64,74,84) };

struct G3L0 { static constexpr int np=3, vout=1, nk=1, oo=0;
  GARR(li,3, 0,1,2) GARR(fo,3, 0,32,80) GARR(mul,3, 32,16,10)
  GARR(cg,3, 0,44,390) GARR(yb,3, 0,1,4) GARR(nj,3, 1,3,5)
  GARR(wo,3, 0,32,48) GARR(uc,3, 0,32,48) };

// ---------------- vectorized global reductions (sm_90+) ----------------
__device__ __forceinline__ void red4(float* p, float a, float b, float c, float d){
  asm volatile("red.global.add.v4.f32 [%0], {%1,%2,%3,%4};"
               :: "l"(p), "f"(a), "f"(b), "f"(c), "f"(d) : "memory");
}
__device__ __forceinline__ void red2(float* p, float a, float b){
  asm volatile("red.global.add.v2.f32 [%0], {%1,%2};"
               :: "l"(p), "f"(a), "f"(b) : "memory");
}

// ---------------- CG construction (replicates reference, fp64 core) ----------------
__device__ double dfact_(int n){ double r=1.0; for (int i=2;i<=n;++i) r*=(double)i; return r; }

__device__ double cg_c(int j1,int m1,int j2,int m2,int j3,int m3){
  if (m1+m2 != m3) return 0.0;
  double pref = sqrt((2.0*j3+1.0)*dfact_(j1+j2-j3)*dfact_(j1-j2+j3)*dfact_(-j1+j2+j3)/dfact_(j1+j2+j3+1));
  pref *= sqrt(dfact_(j1+m1)*dfact_(j1-m1)*dfact_(j2+m2)*dfact_(j2-m2)*dfact_(j3+m3)*dfact_(j3-m3));
  int kmin = 0;
  if (j2-j3-m1 > kmin) kmin = j2-j3-m1;
  if (j1-j3+m2 > kmin) kmin = j1-j3+m2;
  int kmax = j1+j2-j3;
  if (j1-m1 < kmax) kmax = j1-m1;
  if (j2+m2 < kmax) kmax = j2+m2;
  double s = 0.0;
  for (int k=kmin; k<=kmax; ++k){
    double dn = dfact_(k)*dfact_(j1+j2-j3-k)*dfact_(j1-m1-k)*dfact_(j2+m2-k)*dfact_(j3-j2+m1+k)*dfact_(j3-j1-m2+k);
    s += ((k&1)? -1.0 : 1.0)/dn;
  }
  return pref*s;
}

__device__ void qmat_f(int l, float Qr[5][5], float Qi[5][5]){
  for (int a=0;a<5;++a) for (int b=0;b<5;++b){ Qr[a][b]=0.f; Qi[a][b]=0.f; }
  Qr[l][l] = 1.f;
  const float s2 = 0.70710678118654752f;
  for (int m=1;m<=l;++m){
    float sg = (m&1)? -1.f : 1.f;
    Qr[l+m][l+m] = sg*s2;
    Qr[l+m][l-m] = s2;
    Qi[l-m][l-m] = s2;
    Qi[l-m][l+m] = -sg*s2;
  }
}

__global__ void cg_init_kernel(){
  int bid = blockIdx.x, t = threadIdx.x;
  int l1=c_cgL[bid][0], l2=c_cgL[bid][1], l3=c_cgL[bid][2];
  int n1=2*l1+1, n2=2*l2+1, n3=2*l3+1;
  __shared__ float Csh[5][5];
  __shared__ float Q1r[5][5],Q1i[5][5],Q2r[5][5],Q2i[5][5],Q3r[5][5],Q3i[5][5];
  __shared__ float Kr[125], Ki[125];
  __shared__ float s_scale;
  __shared__ int   s_useIm;
  if (t==0){ qmat_f(l1,Q1r,Q1i); qmat_f(l2,Q2r,Q2i); qmat_f(l3,Q3r,Q3i); }
  if (t < n1*n2){
    int a=t/n2, b=t%n2;
    int m1=a-l1, m2=b-l2, m3=m1+m2;
    Csh[a][b] = (m3>=-l3 && m3<=l3) ? (float)cg_c(l1,m1,l2,m2,l3,m3) : 0.f;
  }
  __syncthreads();
  int nel = n1*n2*n3;
  if (t < nel){
    int i=t/(n2*n3), j=(t/n3)%n2, k=t%n3;
    float sr=0.f, si=0.f;
    for (int a=0;a<n1;++a)
      for (int b=0;b<n2;++b){
        float Cv = Csh[a][b];
        if (Cv != 0.f){
          int cc = l3 + (a-l1) + (b-l2);
          float p1r=Q1r[i][a], p1i=-Q1i[i][a];
          float p2r=Q2r[j][b], p2i=-Q2i[j][b];
          float ar=p1r*p2r - p1i*p2i, ai=p1r*p2i + p1i*p2r;
          sr += (ar*Q3r[k][cc] - ai*Q3i[k][cc])*Cv;
          si += (ar*Q3i[k][cc] + ai*Q3r[k][cc])*Cv;
        }
      }
    Kr[t]=sr; Ki[t]=si;
  }
  __syncthreads();
  if (t==0){
    float mR=0.f, mI=0.f;
    for (int q=0;q<nel;++q){ mR=fmaxf(mR,fabsf(Kr[q])); mI=fmaxf(mI,fabsf(Ki[q])); }
    int useIm = (mI > mR);
    float nrm=0.f;
    for (int q=0;q<nel;++q){ float v = useIm ? -Ki[q] : Kr[q]; nrm += v*v; }
    s_scale = sqrtf((float)n3)*rsqrtf(nrm);
    s_useIm = useIm;
  }
  __syncthreads();
  if (t < nel){
    float v = s_useIm ? -Ki[t] : Kr[t];
    g_CG[c_cgPos[bid] + t] = v * s_scale;
  }
}

// ---------------- zero scratch accumulator ----------------
__global__ void zero_t_kernel(){
  int i = blockIdx.x*256 + threadIdx.x;
  if (i < NN*TSTR) g_t[i] = 0.f;
}

// ---------------- radial weight TABLE build: T[r_i] = silu(emb(r_i)@W1)@W2 ----------------
// 64 table rows per block, 256 threads. Same math as the reference radial MLP.
template<int NOUT>
__global__ void tab_build_kernel(const float* __restrict__ W1,    // (10,100)
                                 const float* __restrict__ W2,    // (100,NOUT)
                                 int tab){
  __shared__ float sW1[1000];
  __shared__ float sHid[6400];
  __shared__ float sEmb[640];
  int t = threadIdx.x;
  int r0 = blockIdx.x*64;
  for (int i=t;i<1000;i+=256) sW1[i]=W1[i];
  __syncthreads();
  const float step = 5.0f/11.0f;
  const float pref = 1.14136f * 7.3890560989306495f * 3.1622776601683795f;
  const float hstep = RMAX/(float)(NTAB-1);
  for (int i=t;i<640;i+=256){
    int el=i/10, b=i%10;
    float r = hstep*(float)(r0+el);
    float dd = (r - step*(float)(b+1))/step;
    float t1 = dd+1.f, t2 = 1.f-dd;
    float u1 = (t1>0.f)? expf(-1.f/t1) : 0.f;
    float u2 = (t2>0.f)? expf(-1.f/t2) : 0.f;
    sEmb[i] = pref*u1*u2;
  }
  __syncthreads();
  for (int i=t;i<6400;i+=256){
    int el=i/100, h=i%100;
    float a=0.f;
    #pragma unroll
    for (int b=0;b<10;++b) a += sEmb[el*10+b]*sW1[b*100+h];
    sHid[i] = a/(1.f+expf(-a));
  }
  __syncthreads();
  constexpr int NQ = (NOUT+31)/32;
  int warp = t>>5, lane = t&31;
  int eb = warp*8;
  float acc[8][NQ];
  #pragma unroll
  for (int a=0;a<8;++a)
    #pragma unroll
    for (int q=0;q<NQ;++q) acc[a][q]=0.f;
  #pragma unroll 2
  for (int h=0;h<100;++h){
    float wv[NQ];
    #pragma unroll
    for (int q=0;q<NQ;++q){
      int o = q*32 + lane;
      wv[q] = (o<NOUT)? W2[h*NOUT+o] : 0.f;
    }
    #pragma unroll
    for (int a=0;a<8;++a){
      float f = sHid[(eb+a)*100 + h];
      #pragma unroll
      for (int q=0;q<NQ;++q) acc[a][q] += f*wv[q];
    }
  }
  float* T = g_tab[tab];
  #pragma unroll
  for (int a=0;a<8;++a){
    size_t row = (size_t)(r0 + eb + a);
    #pragma unroll
    for (int q=0;q<NQ;++q){
      int o = q*32 + lane;
      if (o<NOUT) T[row*WSTR + o] = acc[a][q];
    }
  }
}

// ---------------- per-edge radial weights via table interpolation ----------------
template<int NOUT>
__global__ void interp_kernel(const float* __restrict__ evec, int tab){
  __shared__ float sPos[64];
  int t = threadIdx.x;          // 256 threads
  int e0 = blockIdx.x*64;
  if (t < 64){
    int e = e0 + t;
    float vx=evec[3*e], vy=evec[3*e+1], vz=evec[3*e+2];
    float r = sqrtf(vx*vx+vy*vy+vz*vz);
    float p = r * ((float)(NTAB-1)/RMAX);
    sPos[t] = fminf(p, (float)(NTAB-1));
  }
  __syncthreads();
  const float* T = g_tab[tab];
  for (int idx=t; idx<64*NOUT; idx+=256){
    int el = idx/NOUT, o = idx - el*NOUT;
    float p = sPos[el];
    int i = (int)p;
    float fr = p - (float)i;
    int i1 = (i+1 < NTAB)? i+1 : NTAB-1;
    float a = T[(size_t)i*WSTR + o];
    float b = T[(size_t)i1*WSTR + o];
    g_w[(size_t)(e0+el)*WSTR + o] = a + fr*(b-a);
  }
}

// ---------------- fully-unrolled per-group tensor product + linear + scatter ----------------
template<class G>
__device__ __forceinline__ void run_group(const float* __restrict__ sFrow,
                                          const float (&Y)[9],
                                          const float* __restrict__ sCG,
                                          const float* __restrict__ wrow,
                                          const float* __restrict__ lin,
                                          float* __restrict__ obase){
  constexpr int VOUT = G::vout, NK = G::nk;
  float acc[VOUT][NK];
  #pragma unroll
  for (int v=0;v<VOUT;++v)
    #pragma unroll
    for (int k=0;k<NK;++k) acc[v][k]=0.f;
  #pragma unroll
  for (int p=0;p<G::np;++p){
    const int ni = 2*G::li(p)+1;
    float B[5][NK];
    #pragma unroll
    for (int i=0;i<5;++i){
      if (i < ni){
        #pragma unroll
        for (int k=0;k<NK;++k){
          float b=0.f;
          #pragma unroll
          for (int j=0;j<5;++j)
            if (j < G::nj(p)) b += Y[G::yb(p)+j]*sCG[G::cg(p)+(i*G::nj(p)+j)*NK+k];
          B[i][k]=b;
        }
      }
    }
    const float* f = sFrow + G::fo(p);
    const float* w = wrow + G::wo(p);
    const float* L = lin + G::uc(p)*VOUT;
    #pragma unroll 4
    for (int u=0;u<G::mul(p);++u){
      float pw = w[u];
      float m[NK];
      #pragma unroll
      for (int k=0;k<NK;++k){
        float a=0.f;
        #pragma unroll
        for (int i=0;i<5;++i)
          if (i < ni) a += f[u*ni+i]*B[i][k];
        m[k]=a*pw;
      }
      #pragma unroll
      for (int v=0;v<VOUT;++v){
        float lw = L[u*VOUT+v];
        #pragma unroll
        for (int k=0;k<NK;++k) acc[v][k] += lw*m[k];
      }
    }
  }
  constexpr int TOT = VOUT*NK;
  float* fl = &acc[0][0];
  if constexpr (TOT >= 4){
    #pragma unroll
    for (int i=0; i+3<TOT; i+=4)
      red4(obase+i, 0.25f*fl[i], 0.25f*fl[i+1], 0.25f*fl[i+2], 0.25f*fl[i+3]);
  }
  if constexpr ((TOT & 3) >= 2){
    constexpr int b = TOT & ~3;
    red2(obase+b, 0.25f*fl[b], 0.25f*fl[b+1]);
  }
  if constexpr (TOT & 1){
    atomicAdd(obase + (TOT-1), 0.25f*fl[TOT-1]);
  }
}

// ---------------- merged conv kernel: 64 edges/block, f staged in shared ----------------
template<class GA, class GB, class GC, int NG, int FDIM, int FSTR>
__global__ void conv_merged_kernel(const float* __restrict__ evec,
                                   const int* __restrict__ src,
                                   const int* __restrict__ dst,
                                   const float* __restrict__ xin,
                                   int fsel,
                                   const float* __restrict__ linA,
                                   const float* __restrict__ linB,
                                   const float* __restrict__ linC){
  __shared__ float sF[64*FSTR];
  __shared__ float sCG[615];
  __shared__ int sSrc[64];
  int t = threadIdx.x;           // 64 threads
  int e0 = blockIdx.x*64;
  const float* feats = (fsel==0)? xin : ((fsel==1)? g_h1 : g_h2);
  for (int i=t;i<615;i+=64) sCG[i]=g_CG[i];
  sSrc[t]=src[e0+t];
  __syncthreads();
  for (int idx=t; idx<64*FDIM; idx+=64){
    int el=idx/FDIM, c=idx-el*FDIM;
    sF[el*FSTR+c] = feats[(size_t)sSrc[el]*FDIM + c];
  }
  __syncthreads();
  int e = e0 + t;
  float vx=evec[3*e], vy=evec[3*e+1], vz=evec[3*e+2];
  float rn = rsqrtf(vx*vx+vy*vy+vz*vz);
  float X=vx*rn, Yv=vy*rn, Z=vz*rn;
  const float c3=1.7320508075688772f, c15=3.872983346207417f, c5=2.23606797749979f;
  float Y[9] = {1.f, c3*Yv, c3*Z, c3*X,
                c15*X*Yv, c15*Yv*Z, 0.5f*c5*(3.f*Z*Z-1.f), c15*X*Z, 0.5f*c15*(X*X-Yv*Yv)};
  const float* wrow = g_w + (size_t)e*WSTR;
  const float* myF  = sF + t*FSTR;
  int d = dst[e];
  float* tb = g_t + (size_t)d*TSTR;
  run_group<GA>(myF, Y, sCG, wrow, linA, tb + GA::oo);
  if constexpr (NG > 1) run_group<GB>(myF, Y, sCG, wrow, linB, tb + GB::oo);
  if constexpr (NG > 2) run_group<GC>(myF, Y, sCG, wrow, linC, tb + GC::oo);
}

// ---------------- node kernels ----------------
__global__ void post1_kernel(const float* __restrict__ x,
                             const float* __restrict__ sc1,    // (8,32)
                             const float* __restrict__ gw){    // (32,26)
  int n = blockIdx.x*128 + threadIdx.x;
  if (n >= NN) return;
  const float* tin = g_t + (size_t)n*TSTR;
  float xr[8];
  #pragma unroll
  for (int u=0;u<8;++u) xr[u]=x[n*8+u];
  float s0[32];
  #pragma unroll
  for (int v=0;v<32;++v){
    float a = tin[v];
    #pragma unroll
    for (int u=0;u<8;++u) a += xr[u]*sc1[u*32+v];
    s0[v]=a;
  }
  float g[26];
  #pragma unroll
  for (int j=0;j<26;++j){
    float a=0.f;
    #pragma unroll
    for (int v=0;v<32;++v) a += s0[v]*gw[v*26+j];
    g[j]=1.f/(1.f+expf(-a));
  }
  float* ho = g_h1 + (size_t)n*130;
  #pragma unroll
  for (int v=0;v<32;++v) ho[v] = s0[v]/(1.f+expf(-s0[v]));
  #pragma unroll
  for (int v=0;v<16;++v)
    #pragma unroll
    for (int k=0;k<3;++k) ho[32+v*3+k] = tin[32+v*3+k]*g[v];
  #pragma unroll
  for (int v=0;v<10;++v)
    #pragma unroll
    for (int k=0;k<5;++k) ho[80+v*5+k] = tin[80+v*5+k]*g[16+v];
}

__global__ void post2_kernel(const float* __restrict__ sc0,   // (32,32)
                             const float* __restrict__ sc1m,  // (16,16)
                             const float* __restrict__ sc2m,  // (10,10)
                             const float* __restrict__ gw){   // (32,26)
  int n = blockIdx.x*128 + threadIdx.x;
  if (n >= NN) return;
  const float* tin = g_t + (size_t)n*TSTR;
  const float* hp  = g_h1 + (size_t)n*130;
  float h0[32];
  #pragma unroll
  for (int u=0;u<32;++u) h0[u]=hp[u];
  float s0[32];
  #pragma unroll
  for (int v=0;v<32;++v){
    float a = tin[v];
    #pragma unroll
    for (int u=0;u<32;++u) a += h0[u]*sc0[u*32+v];
    s0[v]=a;
  }
  float g[26];
  #pragma unroll
  for (int j=0;j<26;++j){
    float a=0.f;
    #pragma unroll
    for (int v=0;v<32;++v) a += s0[v]*gw[v*26+j];
    g[j]=1.f/(1.f+expf(-a));
  }
  float* ho = g_h2 + (size_t)n*130;
  #pragma unroll
  for (int v=0;v<32;++v) ho[v] = s0[v]/(1.f+expf(-s0[v]));
  #pragma unroll
  for (int v=0;v<16;++v)
    #pragma unroll
    for (int k=0;k<3;++k){
      float a = tin[32+v*3+k];
      #pragma unroll
      for (int u=0;u<16;++u) a += hp[32+u*3+k]*sc1m[u*16+v];
      ho[32+v*3+k] = a*g[v];
    }
  #pragma unroll
  for (int v=0;v<10;++v)
    #pragma unroll
    for (int k=0;k<5;++k){
      float a = tin[80+v*5+k];
      #pragma unroll
      for (int u=0;u<10;++u) a += hp[80+u*5+k]*sc2m[u*10+v];
      ho[80+v*5+k] = a*g[16+v];
    }
}

__global__ void final_kernel(const float* __restrict__ sc3,   // (32,1)
                             float* __restrict__ out){
  int n = blockIdx.x*128 + threadIdx.x;
  if (n >= NN) return;
  float a = g_t[(size_t)n*TSTR];
  const float* hp = g_h2 + (size_t)n*130;
  #pragma unroll
  for (int u=0;u<32;++u) a += hp[u]*sc3[u];
  out[n] = a;
}

// ---------------- launcher ----------------
extern "C" void kernel_launch(void* const* d_in, const int* in_sizes, int n_in,
                              void* d_out, int out_size){
  const float* x      = (const float*)d_in[0];
  const float* evec   = (const float*)d_in[1];
  const float* fc1w1  = (const float*)d_in[2];
  const float* fc1w2  = (const float*)d_in[3];
  const float* lin1l0 = (const float*)d_in[4];
  const float* lin1l1 = (const float*)d_in[5];
  const float* lin1l2 = (const float*)d_in[6];
  const float* sc1l0  = (const float*)d_in[7];
  const float* gate1  = (const float*)d_in[8];
  const float* fc2w1  = (const float*)d_in[9];
  const float* fc2w2  = (const float*)d_in[10];
  const float* lin2l0 = (const float*)d_in[11];
  const float* lin2l1 = (const float*)d_in[12];
  const float* lin2l2 = (const float*)d_in[13];
  const float* sc2l0  = (const float*)d_in[14];
  const float* sc2l1  = (const float*)d_in[15];
  const float* sc2l2  = (const float*)d_in[16];
  const float* gate2  = (const float*)d_in[17];
  const float* fc3w1  = (const float*)d_in[18];
  const float* fc3w2  = (const float*)d_in[19];
  const float* lin3l0 = (const float*)d_in[20];
  const float* sc3l0  = (const float*)d_in[21];
  const int*   esrc   = (const int*)d_in[22];
  const int*   edst   = (const int*)d_in[23];
  float* out = (float*)d_out;

  cg_init_kernel<<<15,128>>>();

  // build radial-weight tables (one per conv)
  tab_build_kernel<24><<<NTAB/64,256>>>(fc1w1, fc1w2, 0);
  tab_build_kernel<252><<<NTAB/64,256>>>(fc2w1, fc2w2, 1);
  tab_build_kernel<58><<<NTAB/64,256>>>(fc3w1, fc3w2, 2);

  // ---- layer 1 ----
  zero_t_kernel<<<(NN*TSTR+255)/256,256>>>();
  interp_kernel<24><<<NE/64,256>>>(evec, 0);
  conv_merged_kernel<G1L0,G1L1,G1L2,3,8,9><<<NE/64,64>>>(
      evec, esrc, edst, x, 0, lin1l0, lin1l1, lin1l2);
  post1_kernel<<<(NN+127)/128,128>>>(x, sc1l0, gate1);

  // ---- layer 2 ----
  zero_t_kernel<<<(NN*TSTR+255)/256,256>>>();
  interp_kernel<252><<<NE/64,256>>>(evec, 1);
  conv_merged_kernel<G2L0,G2L1,G2L2,3,130,131><<<NE/64,64>>>(
      evec, esrc, edst, x, 1, lin2l0, lin2l1, lin2l2);
  post2_kernel<<<(NN+127)/128,128>>>(sc2l0, sc2l1, sc2l2, gate2);

  // ---- layer 3 ----
  zero_t_kernel<<<(NN*TSTR+255)/256,256>>>();
  interp_kernel<58><<<NE/64,256>>>(evec, 2);
  conv_merged_kernel<G3L0,G3L0,G3L0,1,130,131><<<NE/64,64>>>(
      evec, esrc, edst, x, 2, lin3l0, lin3l0, lin3l0);
  final_kernel<<<(NN+127)/128,128>>>(sc3l0, out);
}